// round 5
// baseline (speedup 1.0000x reference)
#include <cuda_runtime.h>
#include <cuda_bf16.h>

// ---------------- problem constants ----------------
#define NN    20000            // nodes
#define NE    320000           // edges (without self loops)
#define ET    (NE + NN)        // edges + self loops = 340000
#define FIN   256
#define HID   32
#define HEADS 8
#define F1    256              // HEADS*HID
#define NC    16
#define NEGSL 0.2f
#define EPSF  1e-16f
#define NINF  (__int_as_float(0xff800000))

// ---------------- device scratch ----------------
__device__ float g_h1  [NN * F1];      // x @ W1
__device__ float g_hx  [NN * F1];      // elu(agg1 + b1)
__device__ float g_as1 [NN * HEADS];
__device__ float g_ad1 [NN * HEADS];
__device__ float g_z2  [NN * NC];      // hx @ W2
__device__ float g_as2 [NN];
__device__ float g_ad2 [NN];
// CSR by destination
__device__ int   g_deg [NN];
__device__ int   g_off [NN];
__device__ int   g_cur [NN];
__device__ int   g_ss  [ET];           // src sorted by dst
__device__ float g_ws  [ET];           // edge weight sorted by dst

// ================= CSR build =================
__global__ void k_zerodeg() {
    int i = blockIdx.x * blockDim.x + threadIdx.x;
    if (i < NN) g_deg[i] = 0;
}

__global__ void k_hist(const int* __restrict__ dst) {
    int e = blockIdx.x * blockDim.x + threadIdx.x;
    if (e >= ET) return;
    int d = (e < NE) ? dst[e] : (e - NE);
    atomicAdd(&g_deg[d], 1);
}

// single-block exclusive scan of g_deg -> g_off, g_cur
__global__ void k_scan() {
    __shared__ int part[256];
    const int C = 79;                       // 256*79 = 20224 >= NN
    int t = threadIdx.x;
    int base = t * C;
    int sum = 0;
    for (int i = 0; i < C; i++) { int idx = base + i; if (idx < NN) sum += g_deg[idx]; }
    part[t] = sum;
    __syncthreads();
    for (int o = 1; o < 256; o <<= 1) {
        int v = (t >= o) ? part[t - o] : 0;
        __syncthreads();
        part[t] += v;
        __syncthreads();
    }
    int run = (t == 0) ? 0 : part[t - 1];
    for (int i = 0; i < C; i++) {
        int idx = base + i;
        if (idx < NN) { g_off[idx] = run; g_cur[idx] = run; run += g_deg[idx]; }
    }
}

__global__ void k_scatter(const int* __restrict__ src, const int* __restrict__ dst,
                          const float* __restrict__ ew) {
    int e = blockIdx.x * blockDim.x + threadIdx.x;
    if (e >= ET) return;
    int s, d; float w;
    if (e < NE) { s = src[e]; d = dst[e]; w = ew[e]; }
    else        { s = d = e - NE; w = 1.0f; }
    int pos = atomicAdd(&g_cur[d], 1);
    g_ss[pos] = s;
    g_ws[pos] = w;
}

// ================= GEMM1: g_h1 = x[NN,256] @ W1[256,256] =================
__global__ void k_gemm1(const float* __restrict__ A, const float* __restrict__ B) {
    __shared__ float As[16][64];
    __shared__ float Bs[16][64];
    const int t  = threadIdx.x;
    const int tx = t & 15, ty = t >> 4;
    const int rowBase = blockIdx.y * 64;
    const int colBase = blockIdx.x * 64;
    const int arow = t >> 2,  acol = (t & 3) * 4;
    const int brow = t >> 4,  bcol = (t & 15) * 4;

    float acc[4][4];
#pragma unroll
    for (int i = 0; i < 4; i++)
#pragma unroll
        for (int j = 0; j < 4; j++) acc[i][j] = 0.0f;

    for (int k0 = 0; k0 < 256; k0 += 16) {
        float4 av = make_float4(0.f, 0.f, 0.f, 0.f);
        int grow = rowBase + arow;
        if (grow < NN) av = *reinterpret_cast<const float4*>(A + grow * 256 + k0 + acol);
        As[acol + 0][arow] = av.x;
        As[acol + 1][arow] = av.y;
        As[acol + 2][arow] = av.z;
        As[acol + 3][arow] = av.w;
        float4 bv = *reinterpret_cast<const float4*>(B + (k0 + brow) * 256 + colBase + bcol);
        *reinterpret_cast<float4*>(&Bs[brow][bcol]) = bv;
        __syncthreads();
#pragma unroll
        for (int k = 0; k < 16; k++) {
            float a0 = As[k][ty * 4 + 0];
            float a1 = As[k][ty * 4 + 1];
            float a2 = As[k][ty * 4 + 2];
            float a3 = As[k][ty * 4 + 3];
            float4 b = *reinterpret_cast<float4*>(&Bs[k][tx * 4]);
            acc[0][0] += a0 * b.x; acc[0][1] += a0 * b.y; acc[0][2] += a0 * b.z; acc[0][3] += a0 * b.w;
            acc[1][0] += a1 * b.x; acc[1][1] += a1 * b.y; acc[1][2] += a1 * b.z; acc[1][3] += a1 * b.w;
            acc[2][0] += a2 * b.x; acc[2][1] += a2 * b.y; acc[2][2] += a2 * b.z; acc[2][3] += a2 * b.w;
            acc[3][0] += a3 * b.x; acc[3][1] += a3 * b.y; acc[3][2] += a3 * b.z; acc[3][3] += a3 * b.w;
        }
        __syncthreads();
    }
#pragma unroll
    for (int i = 0; i < 4; i++) {
        int r = rowBase + ty * 4 + i;
        if (r < NN) {
            float4 v = make_float4(acc[i][0], acc[i][1], acc[i][2], acc[i][3]);
            *reinterpret_cast<float4*>(g_h1 + r * 256 + colBase + tx * 4) = v;
        }
    }
}

// ================= attention scalars layer1: warp per node =================
__global__ void k_att1(const float* __restrict__ att_s, const float* __restrict__ att_d) {
    int node = blockIdx.x * 8 + (threadIdx.x >> 5);
    if (node >= NN) return;
    int lane = threadIdx.x & 31;
    const float* hr = g_h1 + node * F1;
#pragma unroll
    for (int h = 0; h < HEADS; h++) {
        float v = hr[h * 32 + lane];
        float s = v * att_s[h * 32 + lane];
        float d = v * att_d[h * 32 + lane];
#pragma unroll
        for (int o = 16; o; o >>= 1) {
            s += __shfl_xor_sync(0xffffffffu, s, o);
            d += __shfl_xor_sync(0xffffffffu, d, o);
        }
        if (lane == 0) { g_as1[node * 8 + h] = s; g_ad1[node * 8 + h] = d; }
    }
}

// ================= layer1 fused: softmax + aggregate + bias + elu ==========
// warp per destination node; CSR row [off, off+deg)
__global__ void k_l1(const float* __restrict__ b1) {
    int d = blockIdx.x * (blockDim.x >> 5) + (threadIdx.x >> 5);
    if (d >= NN) return;
    int lane  = threadIdx.x & 31;
    int start = g_off[d];
    int deg   = g_deg[d];

    // ---- pass 1: per-head max then denom. lane = (jq=lane>>3, hh=lane&7)
    int hh = lane & 7, jq = lane >> 3;
    float ad_hh = g_ad1[d * 8 + hh];
    float m = NINF;
    for (int j = jq; j < deg; j += 4) {
        int   s = g_ss[start + j];
        float w = g_ws[start + j];
        float v = g_as1[s * 8 + hh] + ad_hh;
        v = (v > 0.0f) ? v : NEGSL * v;
        m = fmaxf(m, v * w);
    }
    m = fmaxf(m, __shfl_xor_sync(0xffffffffu, m, 8));
    m = fmaxf(m, __shfl_xor_sync(0xffffffffu, m, 16));
    float den = 0.0f;
    for (int j = jq; j < deg; j += 4) {
        int   s = g_ss[start + j];
        float w = g_ws[start + j];
        float v = g_as1[s * 8 + hh] + ad_hh;
        v = (v > 0.0f) ? v : NEGSL * v;
        den += expf(v * w - m);
    }
    den += __shfl_xor_sync(0xffffffffu, den, 8);
    den += __shfl_xor_sync(0xffffffffu, den, 16);

    // ---- redistribute: pass2 lane owns head h = lane>>2 (lane h in 0..7 has hh==h)
    int   h    = lane >> 2;
    float mh   = __shfl_sync(0xffffffffu, m, h);
    float inv  = 1.0f / (__shfl_sync(0xffffffffu, den, h) + EPSF);
    float ad_h = __shfl_sync(0xffffffffu, ad_hh, h);

    float acc[8];
#pragma unroll
    for (int k = 0; k < 8; k++) acc[k] = 0.0f;
    int fo = (lane & 3) << 3;                 // 0,8,16,24 within head

    for (int j = 0; j < deg; j++) {
        int   s = g_ss[start + j];
        float w = g_ws[start + j];
        float v = g_as1[s * 8 + h] + ad_h;
        v = (v > 0.0f) ? v : NEGSL * v;
        float alpha = expf(v * w - mh) * inv;
        const float4* p = reinterpret_cast<const float4*>(g_h1 + s * 256 + h * 32 + fo);
        float4 a = p[0];
        float4 b = p[1];
        acc[0] += alpha * a.x; acc[1] += alpha * a.y;
        acc[2] += alpha * a.z; acc[3] += alpha * a.w;
        acc[4] += alpha * b.x; acc[5] += alpha * b.y;
        acc[6] += alpha * b.z; acc[7] += alpha * b.w;
    }

    // feature base for this lane = lane*8 (== h*32 + fo)
    int fb = lane * 8;
#pragma unroll
    for (int k = 0; k < 8; k++) {
        float v = acc[k] + b1[fb + k];
        acc[k] = (v > 0.0f) ? v : (expf(v) - 1.0f);
    }
    float* o = g_hx + d * 256 + fb;
    *reinterpret_cast<float4*>(o)     = make_float4(acc[0], acc[1], acc[2], acc[3]);
    *reinterpret_cast<float4*>(o + 4) = make_float4(acc[4], acc[5], acc[6], acc[7]);
}

// ================= GEMM2 + att2 fused: g_z2 = g_hx @ W2; as2/ad2 ==========
__global__ void k_gemm2(const float* __restrict__ W2,
                        const float* __restrict__ att_s, const float* __restrict__ att_d) {
    __shared__ float Ws[256][16];
    int t = threadIdx.x;
    for (int i = t; i < 256 * 16; i += 256) Ws[i >> 4][i & 15] = W2[i];
    __syncthreads();
    int n = blockIdx.x * 16 + (t >> 4);       // 20000 = 16 * 1250 exact
    int c = t & 15;
    const float* a = g_hx + n * 256;
    float sum = 0.0f;
#pragma unroll 8
    for (int k = 0; k < 256; k++) sum += a[k] * Ws[k][c];
    g_z2[n * 16 + c] = sum;
    // att2: reduce across the 16 lanes of this node (same half-warp)
    float s2 = sum * att_s[c];
    float d2 = sum * att_d[c];
#pragma unroll
    for (int o = 8; o; o >>= 1) {
        s2 += __shfl_xor_sync(0xffffffffu, s2, o);
        d2 += __shfl_xor_sync(0xffffffffu, d2, o);
    }
    if (c == 0) { g_as2[n] = s2; g_ad2[n] = d2; }
}

// ================= layer2 fused: softmax + aggregate + bias ================
__global__ void k_l2(const float* __restrict__ b2, float* __restrict__ out) {
    int d = blockIdx.x * (blockDim.x >> 5) + (threadIdx.x >> 5);
    if (d >= NN) return;
    int lane  = threadIdx.x & 31;
    int start = g_off[d];
    int deg   = g_deg[d];
    float ad = g_ad2[d];

    float m = NINF;
    for (int j = lane; j < deg; j += 32) {
        int   s = g_ss[start + j];
        float w = g_ws[start + j];
        float v = g_as2[s] + ad;
        v = (v > 0.0f) ? v : NEGSL * v;
        m = fmaxf(m, v * w);
    }
#pragma unroll
    for (int o = 16; o; o >>= 1) m = fmaxf(m, __shfl_xor_sync(0xffffffffu, m, o));
    float den = 0.0f;
    for (int j = lane; j < deg; j += 32) {
        int   s = g_ss[start + j];
        float w = g_ws[start + j];
        float v = g_as2[s] + ad;
        v = (v > 0.0f) ? v : NEGSL * v;
        den += expf(v * w - m);
    }
#pragma unroll
    for (int o = 16; o; o >>= 1) den += __shfl_xor_sync(0xffffffffu, den, o);
    float inv = 1.0f / (den + EPSF);

    // aggregate: lane = (jq=lane>>4, c=lane&15)
    int c = lane & 15, jq = lane >> 4;
    float acc = 0.0f;
    for (int j = jq; j < deg; j += 2) {
        int   s = g_ss[start + j];
        float w = g_ws[start + j];
        float v = g_as2[s] + ad;
        v = (v > 0.0f) ? v : NEGSL * v;
        float alpha = expf(v * w - m) * inv;
        acc += alpha * g_z2[s * 16 + c];
    }
    acc += __shfl_xor_sync(0xffffffffu, acc, 16);
    if (lane < 16) out[d * 16 + c] = acc + b2[c];
}

// ================= launch ==================================================
extern "C" void kernel_launch(void* const* d_in, const int* in_sizes, int n_in,
                              void* d_out, int out_size) {
    const float* x    = (const float*)d_in[0];
    const int*   ei   = (const int*)  d_in[1];
    const float* ew   = (const float*)d_in[2];
    const float* W1   = (const float*)d_in[3];
    const float* as1  = (const float*)d_in[4];
    const float* ad1  = (const float*)d_in[5];
    const float* b1   = (const float*)d_in[6];
    const float* W2   = (const float*)d_in[7];
    const float* as2  = (const float*)d_in[8];
    const float* ad2  = (const float*)d_in[9];
    const float* b2   = (const float*)d_in[10];
    float* out = (float*)d_out;
    const int* src = ei;
    const int* dst = ei + NE;

    const int TB = 256;

    // CSR build
    k_zerodeg<<<(NN + TB - 1) / TB, TB>>>();
    k_hist   <<<(ET + TB - 1) / TB, TB>>>(dst);
    k_scan   <<<1, 256>>>();
    k_scatter<<<(ET + TB - 1) / TB, TB>>>(src, dst, ew);

    // layer 1
    dim3 g1(256 / 64, (NN + 63) / 64);
    k_gemm1<<<g1, TB>>>(x, W1);
    k_att1 <<<(NN + 7) / 8, TB>>>(as1, ad1);
    k_l1   <<<(NN + 7) / 8, TB>>>(b1);

    // layer 2
    k_gemm2<<<NN / 16, TB>>>(W2, as2, ad2);
    k_l2   <<<(NN + 7) / 8, TB>>>(b2, out);
}

// round 6
// speedup vs baseline: 1.4000x; 1.4000x over previous
#include <cuda_runtime.h>
#include <cuda_bf16.h>

// ---------------- problem constants ----------------
#define NN    20000            // nodes
#define NE    320000           // edges (without self loops)
#define ET    (NE + NN)        // edges + self loops = 340000
#define FIN   256
#define HID   32
#define HEADS 8
#define F1    256              // HEADS*HID
#define NC    16
#define NEGSL 0.2f
#define EPSF  1e-16f
#define NINF  (__int_as_float(0xff800000))

// ---------------- device scratch ----------------
__device__ float g_h1  [NN * F1];      // x @ W1
__device__ float g_hx  [NN * F1];      // elu(agg1 + b1)
__device__ float g_as1 [NN * HEADS];
__device__ float g_ad1 [NN * HEADS];
__device__ float g_m1  [NN * HEADS];
__device__ float g_den1[NN * HEADS];
__device__ float g_ex1 [ET * HEADS];   // logits -> exp, CSR order
__device__ float g_z2  [NN * NC];      // hx @ W2
__device__ float g_as2 [NN];
__device__ float g_ad2 [NN];
__device__ float g_m2  [NN];
__device__ float g_den2[NN];
__device__ float g_ex2 [ET];
// CSR by destination
__device__ int   g_deg [NN];
__device__ int   g_off [NN];
__device__ int   g_cur [NN];
__device__ int   g_ss  [ET];           // src sorted by dst
__device__ int   g_ds  [ET];           // dst per CSR slot
__device__ float g_ws  [ET];           // edge weight sorted by dst

// ---------------- helpers ----------------
__device__ __forceinline__ void atomicMaxF(float* addr, float v) {
    if (v >= 0.0f) atomicMax(reinterpret_cast<int*>(addr), __float_as_int(v));
    else           atomicMin(reinterpret_cast<unsigned int*>(addr), __float_as_uint(v));
}

// ================= CSR build + softmax-state init =================
__global__ void k_init() {
    int i = blockIdx.x * blockDim.x + threadIdx.x;
    if (i < NN * HEADS) { g_m1[i] = NINF; g_den1[i] = 0.0f; }
    if (i < NN)         { g_m2[i] = NINF; g_den2[i] = 0.0f; g_deg[i] = 0; }
}

__global__ void k_hist(const int* __restrict__ dst) {
    int e = blockIdx.x * blockDim.x + threadIdx.x;
    if (e >= ET) return;
    int d = (e < NE) ? dst[e] : (e - NE);
    atomicAdd(&g_deg[d], 1);
}

// single-block exclusive scan of g_deg -> g_off, g_cur
__global__ void k_scan() {
    __shared__ int part[256];
    const int C = 79;                       // 256*79 = 20224 >= NN
    int t = threadIdx.x;
    int base = t * C;
    int sum = 0;
    for (int i = 0; i < C; i++) { int idx = base + i; if (idx < NN) sum += g_deg[idx]; }
    part[t] = sum;
    __syncthreads();
    for (int o = 1; o < 256; o <<= 1) {
        int v = (t >= o) ? part[t - o] : 0;
        __syncthreads();
        part[t] += v;
        __syncthreads();
    }
    int run = (t == 0) ? 0 : part[t - 1];
    for (int i = 0; i < C; i++) {
        int idx = base + i;
        if (idx < NN) { g_off[idx] = run; g_cur[idx] = run; run += g_deg[idx]; }
    }
}

__global__ void k_scatter(const int* __restrict__ src, const int* __restrict__ dst,
                          const float* __restrict__ ew) {
    int e = blockIdx.x * blockDim.x + threadIdx.x;
    if (e >= ET) return;
    int s, d; float w;
    if (e < NE) { s = src[e]; d = dst[e]; w = ew[e]; }
    else        { s = d = e - NE; w = 1.0f; }
    int pos = atomicAdd(&g_cur[d], 1);
    g_ss[pos] = s;
    g_ds[pos] = d;
    g_ws[pos] = w;
}

// ================= GEMM1: g_h1 = x[NN,256] @ W1[256,256] =================
__global__ void k_gemm1(const float* __restrict__ A, const float* __restrict__ B) {
    __shared__ float As[16][64];
    __shared__ float Bs[16][64];
    const int t  = threadIdx.x;
    const int tx = t & 15, ty = t >> 4;
    const int rowBase = blockIdx.y * 64;
    const int colBase = blockIdx.x * 64;
    const int arow = t >> 2,  acol = (t & 3) * 4;
    const int brow = t >> 4,  bcol = (t & 15) * 4;

    float acc[4][4];
#pragma unroll
    for (int i = 0; i < 4; i++)
#pragma unroll
        for (int j = 0; j < 4; j++) acc[i][j] = 0.0f;

    for (int k0 = 0; k0 < 256; k0 += 16) {
        float4 av = make_float4(0.f, 0.f, 0.f, 0.f);
        int grow = rowBase + arow;
        if (grow < NN) av = *reinterpret_cast<const float4*>(A + grow * 256 + k0 + acol);
        As[acol + 0][arow] = av.x;
        As[acol + 1][arow] = av.y;
        As[acol + 2][arow] = av.z;
        As[acol + 3][arow] = av.w;
        float4 bv = *reinterpret_cast<const float4*>(B + (k0 + brow) * 256 + colBase + bcol);
        *reinterpret_cast<float4*>(&Bs[brow][bcol]) = bv;
        __syncthreads();
#pragma unroll
        for (int k = 0; k < 16; k++) {
            float a0 = As[k][ty * 4 + 0];
            float a1 = As[k][ty * 4 + 1];
            float a2 = As[k][ty * 4 + 2];
            float a3 = As[k][ty * 4 + 3];
            float4 b = *reinterpret_cast<float4*>(&Bs[k][tx * 4]);
            acc[0][0] += a0 * b.x; acc[0][1] += a0 * b.y; acc[0][2] += a0 * b.z; acc[0][3] += a0 * b.w;
            acc[1][0] += a1 * b.x; acc[1][1] += a1 * b.y; acc[1][2] += a1 * b.z; acc[1][3] += a1 * b.w;
            acc[2][0] += a2 * b.x; acc[2][1] += a2 * b.y; acc[2][2] += a2 * b.z; acc[2][3] += a2 * b.w;
            acc[3][0] += a3 * b.x; acc[3][1] += a3 * b.y; acc[3][2] += a3 * b.z; acc[3][3] += a3 * b.w;
        }
        __syncthreads();
    }
#pragma unroll
    for (int i = 0; i < 4; i++) {
        int r = rowBase + ty * 4 + i;
        if (r < NN) {
            float4 v = make_float4(acc[i][0], acc[i][1], acc[i][2], acc[i][3]);
            *reinterpret_cast<float4*>(g_h1 + r * 256 + colBase + tx * 4) = v;
        }
    }
}

// ================= attention scalars layer1: warp per node =================
__global__ void k_att1(const float* __restrict__ att_s, const float* __restrict__ att_d) {
    int node = blockIdx.x * 8 + (threadIdx.x >> 5);
    if (node >= NN) return;
    int lane = threadIdx.x & 31;
    const float* hr = g_h1 + node * F1;
#pragma unroll
    for (int h = 0; h < HEADS; h++) {
        float v = hr[h * 32 + lane];
        float s = v * att_s[h * 32 + lane];
        float d = v * att_d[h * 32 + lane];
#pragma unroll
        for (int o = 16; o; o >>= 1) {
            s += __shfl_xor_sync(0xffffffffu, s, o);
            d += __shfl_xor_sync(0xffffffffu, d, o);
        }
        if (lane == 0) { g_as1[node * 8 + h] = s; g_ad1[node * 8 + h] = d; }
    }
}

// ============ layer1 flat pass 1: logit + segment max (CSR order) ==========
__global__ void k_max1() {
    int idx = blockIdx.x * blockDim.x + threadIdx.x;
    if (idx >= ET * HEADS) return;
    int p = idx >> 3, h = idx & 7;
    int s = g_ss[p], d = g_ds[p];
    float w = g_ws[p];
    float v = g_as1[s * 8 + h] + g_ad1[d * 8 + h];
    v = (v > 0.0f) ? v : NEGSL * v;
    v *= w;
    g_ex1[idx] = v;
    atomicMaxF(&g_m1[d * 8 + h], v);
}

// ============ layer1 flat pass 2: exp + denom ==============================
__global__ void k_exp1() {
    int idx = blockIdx.x * blockDim.x + threadIdx.x;
    if (idx >= ET * HEADS) return;
    int p = idx >> 3, h = idx & 7;
    int d = g_ds[p];
    float ex = expf(g_ex1[idx] - g_m1[d * 8 + h]);
    g_ex1[idx] = ex;
    atomicAdd(&g_den1[d * 8 + h], ex);
}

// ============ layer1 aggregate: block per node, 4 warps split edges ========
// lane owns features [lane*8, lane*8+8); head of lane = lane>>2
__global__ void __launch_bounds__(128) k_agg1(const float* __restrict__ b1) {
    __shared__ float part[4][256];
    int d    = blockIdx.x;
    int lane = threadIdx.x & 31;
    int w    = threadIdx.x >> 5;
    int start = g_off[d];
    int deg   = g_deg[d];
    int h  = lane >> 2;
    float inv = 1.0f / (g_den1[d * 8 + h] + EPSF);

    float acc[8];
#pragma unroll
    for (int k = 0; k < 8; k++) acc[k] = 0.0f;

    for (int j = w; j < deg; j += 4) {
        int   s = g_ss[start + j];
        float alpha = g_ex1[(start + j) * 8 + h] * inv;
        const float4* p = reinterpret_cast<const float4*>(g_h1 + s * 256 + lane * 8);
        float4 a = p[0];
        float4 b = p[1];
        acc[0] += alpha * a.x; acc[1] += alpha * a.y;
        acc[2] += alpha * a.z; acc[3] += alpha * a.w;
        acc[4] += alpha * b.x; acc[5] += alpha * b.y;
        acc[6] += alpha * b.z; acc[7] += alpha * b.w;
    }

    int fb = lane * 8;
    *reinterpret_cast<float4*>(&part[w][fb])     = make_float4(acc[0], acc[1], acc[2], acc[3]);
    *reinterpret_cast<float4*>(&part[w][fb + 4]) = make_float4(acc[4], acc[5], acc[6], acc[7]);
    __syncthreads();

#pragma unroll
    for (int f = threadIdx.x; f < 256; f += 128) {
        float v = part[0][f] + part[1][f] + part[2][f] + part[3][f] + b1[f];
        g_hx[d * 256 + f] = (v > 0.0f) ? v : (expf(v) - 1.0f);
    }
}

// ================= GEMM2 + att2 fused: g_z2 = g_hx @ W2 ====================
__global__ void k_gemm2(const float* __restrict__ W2,
                        const float* __restrict__ att_s, const float* __restrict__ att_d) {
    __shared__ float Ws[256][16];
    int t = threadIdx.x;
    for (int i = t; i < 256 * 16; i += 256) Ws[i >> 4][i & 15] = W2[i];
    __syncthreads();
    int n = blockIdx.x * 16 + (t >> 4);       // 20000 = 16 * 1250 exact
    int c = t & 15;
    const float* a = g_hx + n * 256;
    float sum = 0.0f;
#pragma unroll 8
    for (int k = 0; k < 256; k++) sum += a[k] * Ws[k][c];
    g_z2[n * 16 + c] = sum;
    float s2 = sum * att_s[c];
    float d2 = sum * att_d[c];
#pragma unroll
    for (int o = 8; o; o >>= 1) {
        s2 += __shfl_xor_sync(0xffffffffu, s2, o);
        d2 += __shfl_xor_sync(0xffffffffu, d2, o);
    }
    if (c == 0) { g_as2[n] = s2; g_ad2[n] = d2; }
}

// ============ layer2 flat passes ===========================================
__global__ void k_max2() {
    int e = blockIdx.x * blockDim.x + threadIdx.x;
    if (e >= ET) return;
    int s = g_ss[e], d = g_ds[e];
    float w = g_ws[e];
    float v = g_as2[s] + g_ad2[d];
    v = (v > 0.0f) ? v : NEGSL * v;
    v *= w;
    g_ex2[e] = v;
    atomicMaxF(&g_m2[d], v);
}

__global__ void k_exp2() {
    int e = blockIdx.x * blockDim.x + threadIdx.x;
    if (e >= ET) return;
    int d = g_ds[e];
    float ex = expf(g_ex2[e] - g_m2[d]);
    g_ex2[e] = ex;
    atomicAdd(&g_den2[d], ex);
}

// ============ layer2 aggregate: warp per node + fused bias =================
__global__ void k_agg2(const float* __restrict__ b2, float* __restrict__ out) {
    int d = blockIdx.x * (blockDim.x >> 5) + (threadIdx.x >> 5);
    if (d >= NN) return;
    int lane  = threadIdx.x & 31;
    int start = g_off[d];
    int deg   = g_deg[d];
    float inv = 1.0f / (g_den2[d] + EPSF);
    int c = lane & 15, jq = lane >> 4;
    float acc = 0.0f;
    for (int j = jq; j < deg; j += 2) {
        int s = g_ss[start + j];
        acc += g_ex2[start + j] * inv * g_z2[s * 16 + c];
    }
    acc += __shfl_xor_sync(0xffffffffu, acc, 16);
    if (lane < 16) out[d * 16 + c] = acc + b2[c];
}

// ================= launch ==================================================
extern "C" void kernel_launch(void* const* d_in, const int* in_sizes, int n_in,
                              void* d_out, int out_size) {
    const float* x    = (const float*)d_in[0];
    const int*   ei   = (const int*)  d_in[1];
    const float* ew   = (const float*)d_in[2];
    const float* W1   = (const float*)d_in[3];
    const float* as1  = (const float*)d_in[4];
    const float* ad1  = (const float*)d_in[5];
    const float* b1   = (const float*)d_in[6];
    const float* W2   = (const float*)d_in[7];
    const float* as2  = (const float*)d_in[8];
    const float* ad2  = (const float*)d_in[9];
    const float* b2   = (const float*)d_in[10];
    float* out = (float*)d_out;
    const int* src = ei;
    const int* dst = ei + NE;

    const int TB = 256;

    // CSR build + softmax-state init
    k_init   <<<(NN * HEADS + TB - 1) / TB, TB>>>();
    k_hist   <<<(ET + TB - 1) / TB, TB>>>(dst);
    k_scan   <<<1, 256>>>();
    k_scatter<<<(ET + TB - 1) / TB, TB>>>(src, dst, ew);

    // layer 1
    dim3 g1(256 / 64, (NN + 63) / 64);
    k_gemm1<<<g1, TB>>>(x, W1);
    k_att1 <<<(NN + 7) / 8, TB>>>(as1, ad1);
    k_max1 <<<(ET * HEADS + TB - 1) / TB, TB>>>();
    k_exp1 <<<(ET * HEADS + TB - 1) / TB, TB>>>();
    k_agg1 <<<NN, 128>>>(b1);

    // layer 2
    k_gemm2<<<NN / 16, TB>>>(W2, as2, ad2);
    k_max2 <<<(ET + TB - 1) / TB, TB>>>();
    k_exp2 <<<(ET + TB - 1) / TB, TB>>>();
    k_agg2 <<<(NN + 7) / 8, TB>>>(b2, out);
}

// round 7
// speedup vs baseline: 1.8397x; 1.3140x over previous
#include <cuda_runtime.h>
#include <cuda_bf16.h>

// ---------------- problem constants ----------------
#define NN    20000            // nodes
#define NE    320000           // edges (without self loops)
#define ET    (NE + NN)        // 340000
#define HEADS 8
#define F1    256              // HEADS*HID
#define NC    16
#define NEGSL 0.2f
#define EPSF  1e-16f

// ---------------- device scratch ----------------
__device__ float    g_h1  [NN * F1];      // x @ W1
__device__ float    g_hx  [NN * F1];      // elu(agg1 + b1)
__device__ float    g_as1 [NN * HEADS];
__device__ float    g_ad1 [NN * HEADS];
__device__ float    g_den1[NN * HEADS];
__device__ float    g_ex1 [ET * HEADS];   // exp(logit), CSR order
__device__ float    g_z2  [NN * NC];      // hx @ W2
__device__ float    g_as2 [NN];
__device__ float    g_ad2 [NN];
__device__ float    g_den2[NN];
__device__ float    g_ex2 [ET];
__device__ int      g_deg [NN];
__device__ int      g_off [NN];
__device__ int      g_cur [NN];
__device__ int4     g_edge[ET];           // {src, dst, w_bits, pad} CSR order
__device__ unsigned g_Bfrag[2 * 32 * 16 * 32 * 2];   // W1 in mma fragment layout

// ================= CSR build + softmax-state init =================
__global__ void k_init() {
    int i = blockIdx.x * blockDim.x + threadIdx.x;
    if (i < NN * HEADS) g_den1[i] = 0.0f;
    if (i < NN)        { g_den2[i] = 0.0f; g_deg[i] = 0; }
}

__global__ void k_hist(const int* __restrict__ dst) {
    int e = blockIdx.x * blockDim.x + threadIdx.x;
    if (e >= ET) return;
    int d = (e < NE) ? dst[e] : (e - NE);
    atomicAdd(&g_deg[d], 1);
}

__global__ void k_scan() {
    __shared__ int part[256];
    const int C = 79;                       // 256*79 = 20224 >= NN
    int t = threadIdx.x;
    int base = t * C;
    int sum = 0;
    for (int i = 0; i < C; i++) { int idx = base + i; if (idx < NN) sum += g_deg[idx]; }
    part[t] = sum;
    __syncthreads();
    for (int o = 1; o < 256; o <<= 1) {
        int v = (t >= o) ? part[t - o] : 0;
        __syncthreads();
        part[t] += v;
        __syncthreads();
    }
    int run = (t == 0) ? 0 : part[t - 1];
    for (int i = 0; i < C; i++) {
        int idx = base + i;
        if (idx < NN) { g_off[idx] = run; g_cur[idx] = run; run += g_deg[idx]; }
    }
}

__global__ void k_scatter(const int* __restrict__ src, const int* __restrict__ dst,
                          const float* __restrict__ ew) {
    int e = blockIdx.x * blockDim.x + threadIdx.x;
    if (e >= ET) return;
    int s, d; float w;
    if (e < NE) { s = src[e]; d = dst[e]; w = ew[e]; }
    else        { s = d = e - NE; w = 1.0f; }
    int pos = atomicAdd(&g_cur[d], 1);
    g_edge[pos] = make_int4(s, d, __float_as_int(w), 0);
}

// ================= W1 -> mma fragment layout (one-off, tiny) ===============
__device__ __forceinline__ unsigned f2tf(float f) {
    unsigned r; asm("cvt.rna.tf32.f32 %0, %1;" : "=r"(r) : "f"(f)); return r;
}

__global__ void k_prepB(const float* __restrict__ B) {
    int idx = blockIdx.x * blockDim.x + threadIdx.x;   // 65536
    int k = idx >> 8, n = idx & 255;
    int nb = n >> 7, ln = n & 127;
    int nt = ln >> 3;
    int lane = ((ln & 7) << 2) + (k & 3);
    int reg = ((k & 7) >= 4) ? 1 : 0;
    int kg = k >> 3;
    g_Bfrag[((((nb * 32 + kg) * 16 + nt) * 32 + lane) << 1) + reg] = f2tf(B[k * 256 + n]);
}

// ================= GEMM1 (tf32 tensor cores): g_h1 = x @ W1 ================
// block tile 128x128, 8 warps as 2(m) x 4(n), warp tile 64x32
__global__ void __launch_bounds__(256) k_gemm1(const float* __restrict__ A) {
    // A smem: [mt(8)][ks(2)][reg(4)][lane(32)] tf32 bits
    __shared__ unsigned sA[8 * 2 * 4 * 32];
    const int t    = threadIdx.x;
    const int lane = t & 31;
    const int wid  = t >> 5;
    const int wm   = wid & 1;
    const int wn   = wid >> 1;
    const int m0   = blockIdx.y * 128;
    const int nb   = blockIdx.x;            // n-half (0/1)

    float c[4][4][4];
#pragma unroll
    for (int a = 0; a < 4; a++)
#pragma unroll
        for (int b = 0; b < 4; b++)
#pragma unroll
            for (int r = 0; r < 4; r++) c[a][b][r] = 0.0f;

    const int mA  = t >> 1;                 // 0..127 (two threads per row)
    const int kqA = (t & 1) * 2;            // float4 pair index base

    for (int k0 = 0; k0 < 256; k0 += 16) {
        // ---- stage A tile [128 x 16] into fragment layout ----
#pragma unroll
        for (int q = 0; q < 2; q++) {
            int kq = kqA + q;               // 0..3 -> k offset kq*4
            float4 av = make_float4(0.f, 0.f, 0.f, 0.f);
            int gr = m0 + mA;
            if (gr < NN) av = *reinterpret_cast<const float4*>(A + gr * 256 + k0 + kq * 4);
            int rr  = mA & 15, mt = mA >> 4;
            int ks  = kq >> 1;
            int reg = (rr >> 3) + (kq & 1) * 2;
            int lb  = (rr & 7) * 4;
            unsigned* p = sA + (((mt * 2 + ks) * 4 + reg) * 32 + lb);
            p[0] = f2tf(av.x); p[1] = f2tf(av.y); p[2] = f2tf(av.z); p[3] = f2tf(av.w);
        }
        __syncthreads();

        int kg0 = k0 >> 3;
#pragma unroll
        for (int ks = 0; ks < 2; ks++) {
            unsigned a[4][4], b[4][2];
#pragma unroll
            for (int mi = 0; mi < 4; mi++) {
                int mt = wm * 4 + mi;
#pragma unroll
                for (int r = 0; r < 4; r++)
                    a[mi][r] = sA[((mt * 2 + ks) * 4 + r) * 32 + lane];
            }
#pragma unroll
            for (int ni = 0; ni < 4; ni++) {
                int nt = wn * 4 + ni;
                const unsigned* bp = g_Bfrag +
                    ((((nb * 32 + kg0 + ks) * 16 + nt) * 32 + lane) << 1);
                uint2 bv = *reinterpret_cast<const uint2*>(bp);
                b[ni][0] = bv.x; b[ni][1] = bv.y;
            }
#pragma unroll
            for (int mi = 0; mi < 4; mi++)
#pragma unroll
                for (int ni = 0; ni < 4; ni++) {
                    asm volatile(
                        "mma.sync.aligned.m16n8k8.row.col.f32.tf32.tf32.f32 "
                        "{%0,%1,%2,%3}, {%4,%5,%6,%7}, {%8,%9}, {%0,%1,%2,%3};"
                        : "+f"(c[mi][ni][0]), "+f"(c[mi][ni][1]),
                          "+f"(c[mi][ni][2]), "+f"(c[mi][ni][3])
                        : "r"(a[mi][0]), "r"(a[mi][1]), "r"(a[mi][2]), "r"(a[mi][3]),
                          "r"(b[ni][0]), "r"(b[ni][1]));
                }
        }
        __syncthreads();
    }

    // ---- epilogue: write to g_h1 ----
    int r0 = m0 + wm * 64 + (lane >> 2);
    int c0 = nb * 128 + wn * 32 + (lane & 3) * 2;
#pragma unroll
    for (int mi = 0; mi < 4; mi++) {
        int r = r0 + mi * 16;
#pragma unroll
        for (int ni = 0; ni < 4; ni++) {
            int cc = c0 + ni * 8;
            if (r < NN)
                *reinterpret_cast<float2*>(g_h1 + r * 256 + cc) =
                    make_float2(c[mi][ni][0], c[mi][ni][1]);
            if (r + 8 < NN)
                *reinterpret_cast<float2*>(g_h1 + (r + 8) * 256 + cc) =
                    make_float2(c[mi][ni][2], c[mi][ni][3]);
        }
    }
}

// ================= attention scalars layer1: warp per node =================
__global__ void k_att1(const float* __restrict__ att_s, const float* __restrict__ att_d) {
    int node = blockIdx.x * 8 + (threadIdx.x >> 5);
    if (node >= NN) return;
    int lane = threadIdx.x & 31;
    const float* hr = g_h1 + node * F1;
#pragma unroll
    for (int h = 0; h < HEADS; h++) {
        float v = hr[h * 32 + lane];
        float s = v * att_s[h * 32 + lane];
        float d = v * att_d[h * 32 + lane];
#pragma unroll
        for (int o = 16; o; o >>= 1) {
            s += __shfl_xor_sync(0xffffffffu, s, o);
            d += __shfl_xor_sync(0xffffffffu, d, o);
        }
        if (lane == 0) { g_as1[node * 8 + h] = s; g_ad1[node * 8 + h] = d; }
    }
}

// ============ layer1: exp(logit) + denom (no max: logits bounded) ==========
__global__ void k_exp1() {
    int idx = blockIdx.x * blockDim.x + threadIdx.x;
    if (idx >= ET * HEADS) return;
    int p = idx >> 3, h = idx & 7;
    int4 e = g_edge[p];
    float w = __int_as_float(e.z);
    float v = g_as1[e.x * 8 + h] + g_ad1[e.y * 8 + h];
    v = (v > 0.0f) ? v : NEGSL * v;
    float ex = __expf(v * w);
    g_ex1[idx] = ex;
    atomicAdd(&g_den1[e.y * 8 + h], ex);
}

// ============ layer1 aggregate: block per node, 4 warps split edges ========
__global__ void __launch_bounds__(128) k_agg1(const float* __restrict__ b1) {
    __shared__ float part[4][256];
    int d    = blockIdx.x;
    int lane = threadIdx.x & 31;
    int w    = threadIdx.x >> 5;
    int start = g_off[d];
    int deg   = g_deg[d];
    int h  = lane >> 2;
    float inv = 1.0f / (g_den1[d * 8 + h] + EPSF);

    float acc[8];
#pragma unroll
    for (int k = 0; k < 8; k++) acc[k] = 0.0f;

    for (int j = w; j < deg; j += 4) {
        int   s = g_edge[start + j].x;
        float alpha = g_ex1[(start + j) * 8 + h] * inv;
        const float4* p = reinterpret_cast<const float4*>(g_h1 + s * 256 + lane * 8);
        float4 a = p[0];
        float4 b = p[1];
        acc[0] += alpha * a.x; acc[1] += alpha * a.y;
        acc[2] += alpha * a.z; acc[3] += alpha * a.w;
        acc[4] += alpha * b.x; acc[5] += alpha * b.y;
        acc[6] += alpha * b.z; acc[7] += alpha * b.w;
    }

    int fb = lane * 8;
    *reinterpret_cast<float4*>(&part[w][fb])     = make_float4(acc[0], acc[1], acc[2], acc[3]);
    *reinterpret_cast<float4*>(&part[w][fb + 4]) = make_float4(acc[4], acc[5], acc[6], acc[7]);
    __syncthreads();

    for (int f = threadIdx.x; f < 256; f += 128) {
        float v = part[0][f] + part[1][f] + part[2][f] + part[3][f] + b1[f];
        g_hx[d * 256 + f] = (v > 0.0f) ? v : (__expf(v) - 1.0f);
    }
}

// ================= GEMM2 + att2 fused: g_z2 = g_hx @ W2 ====================
__global__ void k_gemm2(const float* __restrict__ W2,
                        const float* __restrict__ att_s, const float* __restrict__ att_d) {
    __shared__ float Ws[256][16];
    int t = threadIdx.x;
    for (int i = t; i < 256 * 16; i += 256) Ws[i >> 4][i & 15] = W2[i];
    __syncthreads();
    int n = blockIdx.x * 16 + (t >> 4);       // 20000 = 16 * 1250 exact
    int c = t & 15;
    const float* a = g_hx + n * 256;
    float sum = 0.0f;
#pragma unroll 8
    for (int k = 0; k < 256; k++) sum += a[k] * Ws[k][c];
    g_z2[n * 16 + c] = sum;
    float s2 = sum * att_s[c];
    float d2 = sum * att_d[c];
#pragma unroll
    for (int o = 8; o; o >>= 1) {
        s2 += __shfl_xor_sync(0xffffffffu, s2, o);
        d2 += __shfl_xor_sync(0xffffffffu, d2, o);
    }
    if (c == 0) { g_as2[n] = s2; g_ad2[n] = d2; }
}

// ============ layer2: exp(logit) + denom ===================================
__global__ void k_exp2() {
    int e = blockIdx.x * blockDim.x + threadIdx.x;
    if (e >= ET) return;
    int4 ed = g_edge[e];
    float w = __int_as_float(ed.z);
    float v = g_as2[ed.x] + g_ad2[ed.y];
    v = (v > 0.0f) ? v : NEGSL * v;
    float ex = __expf(v * w);
    g_ex2[e] = ex;
    atomicAdd(&g_den2[ed.y], ex);
}

// ============ layer2 aggregate: warp per node + fused bias =================
__global__ void k_agg2(const float* __restrict__ b2, float* __restrict__ out) {
    int d = blockIdx.x * (blockDim.x >> 5) + (threadIdx.x >> 5);
    if (d >= NN) return;
    int lane  = threadIdx.x & 31;
    int start = g_off[d];
    int deg   = g_deg[d];
    float inv = 1.0f / (g_den2[d] + EPSF);
    int c = lane & 15, jq = lane >> 4;
    float acc = 0.0f;
    for (int j = jq; j < deg; j += 2) {
        int s = g_edge[start + j].x;
        acc += g_ex2[start + j] * inv * g_z2[s * 16 + c];
    }
    acc += __shfl_xor_sync(0xffffffffu, acc, 16);
    if (lane < 16) out[d * 16 + c] = acc + b2[c];
}

// ================= launch ==================================================
extern "C" void kernel_launch(void* const* d_in, const int* in_sizes, int n_in,
                              void* d_out, int out_size) {
    const float* x    = (const float*)d_in[0];
    const int*   ei   = (const int*)  d_in[1];
    const float* ew   = (const float*)d_in[2];
    const float* W1   = (const float*)d_in[3];
    const float* as1  = (const float*)d_in[4];
    const float* ad1  = (const float*)d_in[5];
    const float* b1   = (const float*)d_in[6];
    const float* W2   = (const float*)d_in[7];
    const float* as2  = (const float*)d_in[8];
    const float* ad2  = (const float*)d_in[9];
    const float* b2   = (const float*)d_in[10];
    float* out = (float*)d_out;
    const int* src = ei;
    const int* dst = ei + NE;

    const int TB = 256;

    // CSR build + init + W1 fragment prep
    k_init   <<<(NN * HEADS + TB - 1) / TB, TB>>>();
    k_hist   <<<(ET + TB - 1) / TB, TB>>>(dst);
    k_scan   <<<1, 256>>>();
    k_scatter<<<(ET + TB - 1) / TB, TB>>>(src, dst, ew);
    k_prepB  <<<256, 256>>>(W1);

    // layer 1
    dim3 g1(2, (NN + 127) / 128);
    k_gemm1<<<g1, 256>>>(x);
    k_att1 <<<(NN + 7) / 8, TB>>>(as1, ad1);
    k_exp1 <<<(ET * HEADS + TB - 1) / TB, TB>>>();
    k_agg1 <<<NN, 128>>>(b1);

    // layer 2
    k_gemm2<<<NN / 16, TB>>>(W2, as2, ad2);
    k_exp2 <<<(ET + TB - 1) / TB, TB>>>();
    k_agg2 <<<(NN + 7) / 8, TB>>>(b2, out);
}

// round 8
// speedup vs baseline: 2.3513x; 1.2781x over previous
#include <cuda_runtime.h>
#include <cuda_bf16.h>

// ---------------- problem constants ----------------
#define NN    20000            // nodes
#define NE    320000           // edges (without self loops)
#define ET    (NE + NN)        // 340000
#define HEADS 8
#define F1    256              // HEADS*HID
#define NC    16
#define NEGSL 0.2f
#define EPSF  1e-16f

// ---------------- device scratch ----------------
__device__ float    g_h1  [NN * F1];      // x @ W1
__device__ float    g_hx  [NN * F1];      // elu(agg1 + b1)
__device__ float    g_as1 [NN * HEADS];   // accumulated in gemm1 epilogue
__device__ float    g_ad1 [NN * HEADS];
__device__ float    g_z2  [NN * NC];      // hx @ W2
__device__ float    g_as2 [NN];
__device__ float    g_ad2 [NN];
__device__ int      g_deg [NN];
__device__ int      g_off [NN];
__device__ int      g_cur [NN];
__device__ int2     g_edge[ET];           // {src, w_bits} CSR order (dst implicit)
__device__ unsigned g_Bfrag [2 * 32 * 16 * 32 * 2];   // W1 tf32 fragments
__device__ unsigned g_B2hi  [32 * 2 * 32 * 2];        // W2 tf32 hi fragments
__device__ unsigned g_B2lo  [32 * 2 * 32 * 2];        // W2 tf32 lo fragments

__device__ __forceinline__ unsigned f2tf(float f) {
    unsigned r; asm("cvt.rna.tf32.f32 %0, %1;" : "=r"(r) : "f"(f)); return r;
}

// ================= init =================
__global__ void k_init() {
    int i = blockIdx.x * blockDim.x + threadIdx.x;
    if (i < NN * HEADS) { g_as1[i] = 0.0f; g_ad1[i] = 0.0f; }
    if (i < NN)         g_deg[i] = 0;
}

__global__ void k_hist(const int* __restrict__ dst) {
    int e = blockIdx.x * blockDim.x + threadIdx.x;
    if (e >= ET) return;
    int d = (e < NE) ? dst[e] : (e - NE);
    atomicAdd(&g_deg[d], 1);
}

// 1024-thread exclusive scan of g_deg -> g_off, g_cur
__global__ void k_scan() {
    __shared__ int part[1024];
    const int C = 20;                       // 1024*20 = 20480 >= NN
    int t = threadIdx.x;
    int base = t * C;
    int sum = 0;
    for (int i = 0; i < C; i++) { int idx = base + i; if (idx < NN) sum += g_deg[idx]; }
    part[t] = sum;
    __syncthreads();
    for (int o = 1; o < 1024; o <<= 1) {
        int v = (t >= o) ? part[t - o] : 0;
        __syncthreads();
        part[t] += v;
        __syncthreads();
    }
    int run = (t == 0) ? 0 : part[t - 1];
    for (int i = 0; i < C; i++) {
        int idx = base + i;
        if (idx < NN) { g_off[idx] = run; g_cur[idx] = run; run += g_deg[idx]; }
    }
}

__global__ void k_scatter(const int* __restrict__ src, const int* __restrict__ dst,
                          const float* __restrict__ ew) {
    int e = blockIdx.x * blockDim.x + threadIdx.x;
    if (e >= ET) return;
    int s, d; float w;
    if (e < NE) { s = src[e]; d = dst[e]; w = ew[e]; }
    else        { s = d = e - NE; w = 1.0f; }
    int pos = atomicAdd(&g_cur[d], 1);
    g_edge[pos] = make_int2(s, __float_as_int(w));
}

// ================= W1 + W2 -> mma fragment layouts =================
__global__ void k_prep(const float* __restrict__ W1, const float* __restrict__ W2) {
    int idx = blockIdx.x * blockDim.x + threadIdx.x;
    if (idx < 65536) {
        int k = idx >> 8, n = idx & 255;
        int nb = n >> 7, ln = n & 127;
        int nt = ln >> 3;
        int lane = ((ln & 7) << 2) + (k & 3);
        int reg = ((k & 7) >= 4) ? 1 : 0;
        int kg = k >> 3;
        g_Bfrag[((((nb * 32 + kg) * 16 + nt) * 32 + lane) << 1) + reg] = f2tf(W1[k * 256 + n]);
    } else if (idx < 65536 + 4096) {
        int i = idx - 65536;
        int k = i >> 4, n = i & 15;
        int nt = n >> 3;
        int lane = ((n & 7) << 2) + (k & 3);
        int reg = ((k & 7) >= 4) ? 1 : 0;
        int kg = k >> 3;
        int base = (((kg * 2 + nt) * 32 + lane) << 1) + reg;
        float w  = W2[k * 16 + n];
        unsigned hi = f2tf(w);
        g_B2hi[base] = hi;
        g_B2lo[base] = f2tf(w - __uint_as_float(hi));
    }
}

// ===== GEMM1 (tf32 mma) + fused att1 epilogue: g_h1 = x @ W1 =====
// block tile 128x128, 8 warps as 2(m) x 4(n), warp tile 64x32 (= one head)
__global__ void __launch_bounds__(256) k_gemm1(const float* __restrict__ A,
                                               const float* __restrict__ att_s,
                                               const float* __restrict__ att_d) {
    __shared__ unsigned sA[8 * 2 * 4 * 32];
    const int t    = threadIdx.x;
    const int lane = t & 31;
    const int wid  = t >> 5;
    const int wm   = wid & 1;
    const int wn   = wid >> 1;
    const int m0   = blockIdx.y * 128;
    const int nb   = blockIdx.x;            // n-half (0/1)

    float c[4][4][4];
#pragma unroll
    for (int a = 0; a < 4; a++)
#pragma unroll
        for (int b = 0; b < 4; b++)
#pragma unroll
            for (int r = 0; r < 4; r++) c[a][b][r] = 0.0f;

    const int mA  = t >> 1;
    const int kqA = (t & 1) * 2;

    for (int k0 = 0; k0 < 256; k0 += 16) {
#pragma unroll
        for (int q = 0; q < 2; q++) {
            int kq = kqA + q;
            float4 av = make_float4(0.f, 0.f, 0.f, 0.f);
            int gr = m0 + mA;
            if (gr < NN) av = *reinterpret_cast<const float4*>(A + gr * 256 + k0 + kq * 4);
            int rr  = mA & 15, mt = mA >> 4;
            int ks  = kq >> 1;
            int reg = (rr >> 3) + (kq & 1) * 2;
            int lb  = (rr & 7) * 4;
            unsigned* p = sA + (((mt * 2 + ks) * 4 + reg) * 32 + lb);
            p[0] = f2tf(av.x); p[1] = f2tf(av.y); p[2] = f2tf(av.z); p[3] = f2tf(av.w);
        }
        __syncthreads();

        int kg0 = k0 >> 3;
#pragma unroll
        for (int ks = 0; ks < 2; ks++) {
            unsigned a[4][4], b[4][2];
#pragma unroll
            for (int mi = 0; mi < 4; mi++) {
                int mt = wm * 4 + mi;
#pragma unroll
                for (int r = 0; r < 4; r++)
                    a[mi][r] = sA[((mt * 2 + ks) * 4 + r) * 32 + lane];
            }
#pragma unroll
            for (int ni = 0; ni < 4; ni++) {
                int nt = wn * 4 + ni;
                const unsigned* bp = g_Bfrag +
                    ((((nb * 32 + kg0 + ks) * 16 + nt) * 32 + lane) << 1);
                uint2 bv = *reinterpret_cast<const uint2*>(bp);
                b[ni][0] = bv.x; b[ni][1] = bv.y;
            }
#pragma unroll
            for (int mi = 0; mi < 4; mi++)
#pragma unroll
                for (int ni = 0; ni < 4; ni++) {
                    asm volatile(
                        "mma.sync.aligned.m16n8k8.row.col.f32.tf32.tf32.f32 "
                        "{%0,%1,%2,%3}, {%4,%5,%6,%7}, {%8,%9}, {%0,%1,%2,%3};"
                        : "+f"(c[mi][ni][0]), "+f"(c[mi][ni][1]),
                          "+f"(c[mi][ni][2]), "+f"(c[mi][ni][3])
                        : "r"(a[mi][0]), "r"(a[mi][1]), "r"(a[mi][2]), "r"(a[mi][3]),
                          "r"(b[ni][0]), "r"(b[ni][1]));
                }
        }
        __syncthreads();
    }

    // ---- epilogue: write g_h1 + fused att1 partials ----
    int r0 = m0 + wm * 64 + (lane >> 2);
    int c0 = nb * 128 + wn * 32 + (lane & 3) * 2;
#pragma unroll
    for (int mi = 0; mi < 4; mi++) {
        int r = r0 + mi * 16;
#pragma unroll
        for (int ni = 0; ni < 4; ni++) {
            int cc = c0 + ni * 8;
            if (r < NN)
                *reinterpret_cast<float2*>(g_h1 + r * 256 + cc) =
                    make_float2(c[mi][ni][0], c[mi][ni][1]);
            if (r + 8 < NN)
                *reinterpret_cast<float2*>(g_h1 + (r + 8) * 256 + cc) =
                    make_float2(c[mi][ni][2], c[mi][ni][3]);
        }
    }

    // att1: this warp's 32 cols == head (nb*4 + wn)
    int head = nb * 4 + wn;
    float asv[8], adv[8];
#pragma unroll
    for (int ni = 0; ni < 4; ni++)
#pragma unroll
        for (int b = 0; b < 2; b++) {
            asv[ni * 2 + b] = att_s[c0 + ni * 8 + b];
            adv[ni * 2 + b] = att_d[c0 + ni * 8 + b];
        }
    float ssum[8], dsum[8];
#pragma unroll
    for (int mi = 0; mi < 4; mi++)
#pragma unroll
        for (int half = 0; half < 2; half++) {
            float s = 0.f, dd = 0.f;
#pragma unroll
            for (int ni = 0; ni < 4; ni++)
#pragma unroll
                for (int b = 0; b < 2; b++) {
                    float v = c[mi][ni][half * 2 + b];
                    s  += v * asv[ni * 2 + b];
                    dd += v * adv[ni * 2 + b];
                }
            ssum[mi * 2 + half] = s;
            dsum[mi * 2 + half] = dd;
        }
#pragma unroll
    for (int i = 0; i < 8; i++) {
        ssum[i] += __shfl_xor_sync(0xffffffffu, ssum[i], 1);
        ssum[i] += __shfl_xor_sync(0xffffffffu, ssum[i], 2);
        dsum[i] += __shfl_xor_sync(0xffffffffu, dsum[i], 1);
        dsum[i] += __shfl_xor_sync(0xffffffffu, dsum[i], 2);
    }
    if ((lane & 3) == 0) {
#pragma unroll
        for (int mi = 0; mi < 4; mi++)
#pragma unroll
            for (int half = 0; half < 2; half++) {
                int r = r0 + mi * 16 + half * 8;
                if (r < NN) {
                    atomicAdd(&g_as1[r * 8 + head], ssum[mi * 2 + half]);
                    atomicAdd(&g_ad1[r * 8 + head], dsum[mi * 2 + half]);
                }
            }
    }
}

// ===== layer1 aggregate with fused softmax: block(128) per node =====
__global__ void __launch_bounds__(128) k_agg1(const float* __restrict__ b1) {
    __shared__ float part[4][256];
    __shared__ float sp[4][8];
    __shared__ float sinv[8];
    int d = blockIdx.x;
    int t = threadIdx.x;
    int start = g_off[d];
    int deg   = g_deg[d];

    // ---- pass A: per-head denominator (no atomics, no stored exp) ----
    int hh = t & 7;
    float ad = g_ad1[d * 8 + hh];
    float den = 0.0f;
    for (int j = t >> 3; j < deg; j += 16) {
        int2 e = g_edge[start + j];
        float w = __int_as_float(e.y);
        float v = g_as1[e.x * 8 + hh] + ad;
        v = (v > 0.0f) ? v : NEGSL * v;
        den += __expf(v * w);
    }
    den += __shfl_xor_sync(0xffffffffu, den, 8);
    den += __shfl_xor_sync(0xffffffffu, den, 16);
    if ((t & 31) < 8) sp[t >> 5][hh] = den;
    __syncthreads();
    if (t < 8) sinv[t] = 1.0f / (sp[0][t] + sp[1][t] + sp[2][t] + sp[3][t] + EPSF);
    __syncthreads();

    // ---- pass B: aggregate; lane owns features [lane*8, lane*8+8) ----
    int lane = t & 31;
    int wrp  = t >> 5;
    int h = lane >> 2;
    float inv = sinv[h];
    float adh = g_ad1[d * 8 + h];

    float acc[8];
#pragma unroll
    for (int k = 0; k < 8; k++) acc[k] = 0.0f;

    for (int j = wrp; j < deg; j += 4) {
        int2 e = g_edge[start + j];
        float ew = __int_as_float(e.y);
        float v = g_as1[e.x * 8 + h] + adh;
        v = (v > 0.0f) ? v : NEGSL * v;
        float alpha = __expf(v * ew) * inv;
        const float4* p = reinterpret_cast<const float4*>(g_h1 + e.x * 256 + lane * 8);
        float4 a = p[0];
        float4 b = p[1];
        acc[0] += alpha * a.x; acc[1] += alpha * a.y;
        acc[2] += alpha * a.z; acc[3] += alpha * a.w;
        acc[4] += alpha * b.x; acc[5] += alpha * b.y;
        acc[6] += alpha * b.z; acc[7] += alpha * b.w;
    }

    int fb = lane * 8;
    *reinterpret_cast<float4*>(&part[wrp][fb])     = make_float4(acc[0], acc[1], acc[2], acc[3]);
    *reinterpret_cast<float4*>(&part[wrp][fb + 4]) = make_float4(acc[4], acc[5], acc[6], acc[7]);
    __syncthreads();

    for (int f = t; f < 256; f += 128) {
        float v = part[0][f] + part[1][f] + part[2][f] + part[3][f] + b1[f];
        g_hx[d * 256 + f] = (v > 0.0f) ? v : (__expf(v) - 1.0f);
    }
}

// ===== GEMM2 (3xTF32 mma) + fused att2: g_z2 = g_hx @ W2 =====
// warp per 16 nodes; K=256 (32 k-groups), N=16 (2 n-tiles)
__global__ void __launch_bounds__(128) k_gemm2(const float* __restrict__ att_s,
                                               const float* __restrict__ att_d) {
    int wg = blockIdx.x * 4 + (threadIdx.x >> 5);
    if (wg >= NN / 16) return;
    int lane = threadIdx.x & 31;
    int m0 = wg * 16;
    int r  = lane >> 2;
    int cq = lane & 3;

    float c[2][4];
#pragma unroll
    for (int nt = 0; nt < 2; nt++)
#pragma unroll
        for (int i = 0; i < 4; i++) c[nt][i] = 0.0f;

    const float* A0 = g_hx + (m0 + r) * 256 + cq;
    const float* A1 = g_hx + (m0 + r + 8) * 256 + cq;

#pragma unroll 4
    for (int kg = 0; kg < 32; kg++) {
        float f0 = A0[kg * 8],     f1 = A1[kg * 8];
        float f2 = A0[kg * 8 + 4], f3 = A1[kg * 8 + 4];
        unsigned h0 = f2tf(f0), h1 = f2tf(f1), h2 = f2tf(f2), h3 = f2tf(f3);
        unsigned l0 = f2tf(f0 - __uint_as_float(h0));
        unsigned l1 = f2tf(f1 - __uint_as_float(h1));
        unsigned l2 = f2tf(f2 - __uint_as_float(h2));
        unsigned l3 = f2tf(f3 - __uint_as_float(h3));
#pragma unroll
        for (int nt = 0; nt < 2; nt++) {
            int fidx = (((kg * 2 + nt) * 32 + lane) << 1);
            uint2 bh = *reinterpret_cast<const uint2*>(g_B2hi + fidx);
            uint2 bl = *reinterpret_cast<const uint2*>(g_B2lo + fidx);
            asm volatile(
                "mma.sync.aligned.m16n8k8.row.col.f32.tf32.tf32.f32 "
                "{%0,%1,%2,%3}, {%4,%5,%6,%7}, {%8,%9}, {%0,%1,%2,%3};"
                : "+f"(c[nt][0]), "+f"(c[nt][1]), "+f"(c[nt][2]), "+f"(c[nt][3])
                : "r"(h0), "r"(h1), "r"(h2), "r"(h3), "r"(bh.x), "r"(bh.y));
            asm volatile(
                "mma.sync.aligned.m16n8k8.row.col.f32.tf32.tf32.f32 "
                "{%0,%1,%2,%3}, {%4,%5,%6,%7}, {%8,%9}, {%0,%1,%2,%3};"
                : "+f"(c[nt][0]), "+f"(c[nt][1]), "+f"(c[nt][2]), "+f"(c[nt][3])
                : "r"(l0), "r"(l1), "r"(l2), "r"(l3), "r"(bh.x), "r"(bh.y));
            asm volatile(
                "mma.sync.aligned.m16n8k8.row.col.f32.tf32.tf32.f32 "
                "{%0,%1,%2,%3}, {%4,%5,%6,%7}, {%8,%9}, {%0,%1,%2,%3};"
                : "+f"(c[nt][0]), "+f"(c[nt][1]), "+f"(c[nt][2]), "+f"(c[nt][3])
                : "r"(h0), "r"(h1), "r"(h2), "r"(h3), "r"(bl.x), "r"(bl.y));
        }
    }

    // write z2
#pragma unroll
    for (int nt = 0; nt < 2; nt++) {
        *reinterpret_cast<float2*>(g_z2 + (m0 + r) * 16 + nt * 8 + cq * 2) =
            make_float2(c[nt][0], c[nt][1]);
        *reinterpret_cast<float2*>(g_z2 + (m0 + r + 8) * 16 + nt * 8 + cq * 2) =
            make_float2(c[nt][2], c[nt][3]);
    }

    // fused att2
    float sA = 0.f, dA = 0.f, sB = 0.f, dB = 0.f;
#pragma unroll
    for (int nt = 0; nt < 2; nt++)
#pragma unroll
        for (int b = 0; b < 2; b++) {
            int col = nt * 8 + cq * 2 + b;
            float as_ = att_s[col], ad_ = att_d[col];
            sA += c[nt][b]     * as_;  dA += c[nt][b]     * ad_;
            sB += c[nt][2 + b] * as_;  dB += c[nt][2 + b] * ad_;
        }
    sA += __shfl_xor_sync(0xffffffffu, sA, 1); sA += __shfl_xor_sync(0xffffffffu, sA, 2);
    dA += __shfl_xor_sync(0xffffffffu, dA, 1); dA += __shfl_xor_sync(0xffffffffu, dA, 2);
    sB += __shfl_xor_sync(0xffffffffu, sB, 1); sB += __shfl_xor_sync(0xffffffffu, sB, 2);
    dB += __shfl_xor_sync(0xffffffffu, dB, 1); dB += __shfl_xor_sync(0xffffffffu, dB, 2);
    if (cq == 0) {
        g_as2[m0 + r]     = sA;  g_ad2[m0 + r]     = dA;
        g_as2[m0 + r + 8] = sB;  g_ad2[m0 + r + 8] = dB;
    }
}

// ===== layer2 aggregate with fused softmax: warp per node =====
__global__ void k_agg2(const float* __restrict__ b2, float* __restrict__ out) {
    int d = blockIdx.x * (blockDim.x >> 5) + (threadIdx.x >> 5);
    if (d >= NN) return;
    int lane  = threadIdx.x & 31;
    int start = g_off[d];
    int deg   = g_deg[d];
    float ad = g_ad2[d];

    float den = 0.0f;
    for (int j = lane; j < deg; j += 32) {
        int2 e = g_edge[start + j];
        float w = __int_as_float(e.y);
        float v = g_as2[e.x] + ad;
        v = (v > 0.0f) ? v : NEGSL * v;
        den += __expf(v * w);
    }
#pragma unroll
    for (int o = 16; o; o >>= 1) den += __shfl_xor_sync(0xffffffffu, den, o);
    float inv = 1.0f / (den + EPSF);

    int c = lane & 15, jq = lane >> 4;
    float acc = 0.0f;
    for (int j = jq; j < deg; j += 2) {
        int2 e = g_edge[start + j];
        float w = __int_as_float(e.y);
        float v = g_as2[e.x] + ad;
        v = (v > 0.0f) ? v : NEGSL * v;
        float alpha = __expf(v * w) * inv;
        acc += alpha * g_z2[e.x * 16 + c];
    }
    acc += __shfl_xor_sync(0xffffffffu, acc, 16);
    if (lane < 16) out[d * 16 + c] = acc + b2[c];
}

// ================= launch ==================================================
extern "C" void kernel_launch(void* const* d_in, const int* in_sizes, int n_in,
                              void* d_out, int out_size) {
    const float* x    = (const float*)d_in[0];
    const int*   ei   = (const int*)  d_in[1];
    const float* ew   = (const float*)d_in[2];
    const float* W1   = (const float*)d_in[3];
    const float* as1  = (const float*)d_in[4];
    const float* ad1  = (const float*)d_in[5];
    const float* b1   = (const float*)d_in[6];
    const float* W2   = (const float*)d_in[7];
    const float* as2  = (const float*)d_in[8];
    const float* ad2  = (const float*)d_in[9];
    const float* b2   = (const float*)d_in[10];
    float* out = (float*)d_out;
    const int* src = ei;
    const int* dst = ei + NE;

    const int TB = 256;

    k_init   <<<(NN * HEADS + TB - 1) / TB, TB>>>();
    k_hist   <<<(ET + TB - 1) / TB, TB>>>(dst);
    k_scan   <<<1, 1024>>>();
    k_scatter<<<(ET + TB - 1) / TB, TB>>>(src, dst, ew);
    k_prep   <<<(65536 + 4096 + TB - 1) / TB, TB>>>(W1, W2);

    dim3 g1(2, (NN + 127) / 128);
    k_gemm1<<<g1, 256>>>(x, as1, ad1);
    k_agg1 <<<NN, 128>>>(b1);

    k_gemm2<<<(NN / 16 + 3) / 4, 128>>>(as2, ad2);
    k_agg2 <<<(NN + 7) / 8, TB>>>(b2, out);
}

// round 12
// speedup vs baseline: 2.9780x; 1.2666x over previous
#include <cuda_runtime.h>
#include <cuda_bf16.h>

// ---------------- problem constants ----------------
#define NN    20000            // nodes
#define NE    320000           // edges (without self loops)
#define ET    (NE + NN)        // 340000
#define HEADS 8
#define F1    256              // HEADS*HID
#define NC    16
#define NEGSL 0.2f
#define EPSF  1e-16f

// ---------------- device scratch ----------------
__device__ float    g_h1  [NN * F1];      // x @ W1
__device__ float    g_hx  [NN * F1];      // elu(agg1 + b1)
__device__ float    g_as1 [NN * HEADS];   // accumulated in gemm1 epilogue
__device__ float    g_ad1 [NN * HEADS];
__device__ float    g_z2  [NN * NC];      // hx @ W2
__device__ float    g_as2 [NN];
__device__ float    g_ad2 [NN];
__device__ int      g_deg [NN];
__device__ int      g_off [NN];
__device__ int      g_cur [NN];
__device__ int2     g_edge[ET];           // {src, w_bits} CSR order (dst implicit)
__device__ unsigned g_Bfrag [2 * 32 * 16 * 32 * 2];   // W1 tf32 fragments
__device__ unsigned g_B2hi  [32 * 2 * 32 * 2];        // W2 tf32 hi fragments
__device__ unsigned g_B2lo  [32 * 2 * 32 * 2];        // W2 tf32 lo fragments

__device__ __forceinline__ unsigned f2tf(float f) {
    unsigned r; asm("cvt.rna.tf32.f32 %0, %1;" : "=r"(r) : "f"(f)); return r;
}

// ====== stream-1 prep: W1/W2 fragment conversion + as1/ad1 zero ======
#define PREP_W1 65536
#define PREP_W2 4096
#define PREP_AS (NN * HEADS)
__global__ void k_pre(const float* __restrict__ W1, const float* __restrict__ W2) {
    int idx = blockIdx.x * blockDim.x + threadIdx.x;
    if (idx < PREP_W1) {
        int k = idx >> 8, n = idx & 255;
        int nb = n >> 7, ln = n & 127;
        int nt = ln >> 3;
        int lane = ((ln & 7) << 2) + (k & 3);
        int reg = ((k & 7) >= 4) ? 1 : 0;
        int kg = k >> 3;
        g_Bfrag[((((nb * 32 + kg) * 16 + nt) * 32 + lane) << 1) + reg] = f2tf(W1[k * 256 + n]);
    } else if (idx < PREP_W1 + PREP_W2) {
        int i = idx - PREP_W1;
        int k = i >> 4, n = i & 15;
        int nt = n >> 3;
        int lane = ((n & 7) << 2) + (k & 3);
        int reg = ((k & 7) >= 4) ? 1 : 0;
        int kg = k >> 3;
        int base = (((kg * 2 + nt) * 32 + lane) << 1) + reg;
        float w  = W2[k * 16 + n];
        unsigned hi = f2tf(w);
        g_B2hi[base] = hi;
        g_B2lo[base] = f2tf(w - __uint_as_float(hi));
    } else if (idx < PREP_W1 + PREP_W2 + PREP_AS) {
        int i = idx - PREP_W1 - PREP_W2;
        g_as1[i] = 0.0f;
        g_ad1[i] = 0.0f;
    }
}

// ====== stream-2: CSR build ======
__global__ void k_initdeg() {
    int i = blockIdx.x * blockDim.x + threadIdx.x;
    if (i < NN) g_deg[i] = 0;
}

__global__ void k_hist(const int* __restrict__ dst) {
    int e = blockIdx.x * blockDim.x + threadIdx.x;
    if (e >= ET) return;
    int d = (e < NE) ? dst[e] : (e - NE);
    atomicAdd(&g_deg[d], 1);
}

__global__ void k_scan() {
    __shared__ int part[1024];
    const int C = 20;                       // 1024*20 = 20480 >= NN
    int t = threadIdx.x;
    int base = t * C;
    int sum = 0;
    for (int i = 0; i < C; i++) { int idx = base + i; if (idx < NN) sum += g_deg[idx]; }
    part[t] = sum;
    __syncthreads();
    for (int o = 1; o < 1024; o <<= 1) {
        int v = (t >= o) ? part[t - o] : 0;
        __syncthreads();
        part[t] += v;
        __syncthreads();
    }
    int run = (t == 0) ? 0 : part[t - 1];
    for (int i = 0; i < C; i++) {
        int idx = base + i;
        if (idx < NN) { g_off[idx] = run; g_cur[idx] = run; run += g_deg[idx]; }
    }
}

__global__ void k_scatter(const int* __restrict__ src, const int* __restrict__ dst,
                          const float* __restrict__ ew) {
    int e = blockIdx.x * blockDim.x + threadIdx.x;
    if (e >= ET) return;
    int s, d; float w;
    if (e < NE) { s = src[e]; d = dst[e]; w = ew[e]; }
    else        { s = d = e - NE; w = 1.0f; }
    int pos = atomicAdd(&g_cur[d], 1);
    g_edge[pos] = make_int2(s, __float_as_int(w));
}

// ===== GEMM1 (tf32 mma) + fused att1 epilogue: g_h1 = x @ W1 =====
// block tile 128x128, 8 warps as 2(m) x 4(n), warp tile 64x32 (= one head)
__global__ void __launch_bounds__(256) k_gemm1(const float* __restrict__ A,
                                               const float* __restrict__ att_s,
                                               const float* __restrict__ att_d) {
    __shared__ unsigned sA[8 * 2 * 4 * 32];
    const int t    = threadIdx.x;
    const int lane = t & 31;
    const int wid  = t >> 5;
    const int wm   = wid & 1;
    const int wn   = wid >> 1;
    const int m0   = blockIdx.y * 128;
    const int nb   = blockIdx.x;            // n-half (0/1)

    float c[4][4][4];
#pragma unroll
    for (int a = 0; a < 4; a++)
#pragma unroll
        for (int b = 0; b < 4; b++)
#pragma unroll
            for (int r = 0; r < 4; r++) c[a][b][r] = 0.0f;

    const int mA  = t >> 1;
    const int kqA = (t & 1) * 2;

    for (int k0 = 0; k0 < 256; k0 += 16) {
#pragma unroll
        for (int q = 0; q < 2; q++) {
            int kq = kqA + q;
            float4 av = make_float4(0.f, 0.f, 0.f, 0.f);
            int gr = m0 + mA;
            if (gr < NN) av = *reinterpret_cast<const float4*>(A + gr * 256 + k0 + kq * 4);
            int rr  = mA & 15, mt = mA >> 4;
            int ks  = kq >> 1;
            int reg = (rr >> 3) + (kq & 1) * 2;
            int lb  = (rr & 7) * 4;
            unsigned* p = sA + (((mt * 2 + ks) * 4 + reg) * 32 + lb);
            p[0] = f2tf(av.x); p[1] = f2tf(av.y); p[2] = f2tf(av.z); p[3] = f2tf(av.w);
        }
        __syncthreads();

        int kg0 = k0 >> 3;
#pragma unroll
        for (int ks = 0; ks < 2; ks++) {
            unsigned a[4][4], b[4][2];
#pragma unroll
            for (int mi = 0; mi < 4; mi++) {
                int mt = wm * 4 + mi;
#pragma unroll
                for (int r = 0; r < 4; r++)
                    a[mi][r] = sA[((mt * 2 + ks) * 4 + r) * 32 + lane];
            }
#pragma unroll
            for (int ni = 0; ni < 4; ni++) {
                int nt = wn * 4 + ni;
                const unsigned* bp = g_Bfrag +
                    ((((nb * 32 + kg0 + ks) * 16 + nt) * 32 + lane) << 1);
                uint2 bv = *reinterpret_cast<const uint2*>(bp);
                b[ni][0] = bv.x; b[ni][1] = bv.y;
            }
#pragma unroll
            for (int mi = 0; mi < 4; mi++)
#pragma unroll
                for (int ni = 0; ni < 4; ni++) {
                    asm volatile(
                        "mma.sync.aligned.m16n8k8.row.col.f32.tf32.tf32.f32 "
                        "{%0,%1,%2,%3}, {%4,%5,%6,%7}, {%8,%9}, {%0,%1,%2,%3};"
                        : "+f"(c[mi][ni][0]), "+f"(c[mi][ni][1]),
                          "+f"(c[mi][ni][2]), "+f"(c[mi][ni][3])
                        : "r"(a[mi][0]), "r"(a[mi][1]), "r"(a[mi][2]), "r"(a[mi][3]),
                          "r"(b[ni][0]), "r"(b[ni][1]));
                }
        }
        __syncthreads();
    }

    // ---- epilogue: write g_h1 + fused att1 partials ----
    int r0 = m0 + wm * 64 + (lane >> 2);
    int c0 = nb * 128 + wn * 32 + (lane & 3) * 2;
#pragma unroll
    for (int mi = 0; mi < 4; mi++) {
        int r = r0 + mi * 16;
#pragma unroll
        for (int ni = 0; ni < 4; ni++) {
            int cc = c0 + ni * 8;
            if (r < NN)
                *reinterpret_cast<float2*>(g_h1 + r * 256 + cc) =
                    make_float2(c[mi][ni][0], c[mi][ni][1]);
            if (r + 8 < NN)
                *reinterpret_cast<float2*>(g_h1 + (r + 8) * 256 + cc) =
                    make_float2(c[mi][ni][2], c[mi][ni][3]);
        }
    }

    int head = nb * 4 + wn;
    float asv[8], adv[8];
#pragma unroll
    for (int ni = 0; ni < 4; ni++)
#pragma unroll
        for (int b = 0; b < 2; b++) {
            asv[ni * 2 + b] = att_s[c0 + ni * 8 + b];
            adv[ni * 2 + b] = att_d[c0 + ni * 8 + b];
        }
    float ssum[8], dsum[8];
#pragma unroll
    for (int mi = 0; mi < 4; mi++)
#pragma unroll
        for (int half = 0; half < 2; half++) {
            float s = 0.f, dd = 0.f;
#pragma unroll
            for (int ni = 0; ni < 4; ni++)
#pragma unroll
                for (int b = 0; b < 2; b++) {
                    float v = c[mi][ni][half * 2 + b];
                    s  += v * asv[ni * 2 + b];
                    dd += v * adv[ni * 2 + b];
                }
            ssum[mi * 2 + half] = s;
            dsum[mi * 2 + half] = dd;
        }
#pragma unroll
    for (int i = 0; i < 8; i++) {
        ssum[i] += __shfl_xor_sync(0xffffffffu, ssum[i], 1);
        ssum[i] += __shfl_xor_sync(0xffffffffu, ssum[i], 2);
        dsum[i] += __shfl_xor_sync(0xffffffffu, dsum[i], 1);
        dsum[i] += __shfl_xor_sync(0xffffffffu, dsum[i], 2);
    }
    if ((lane & 3) == 0) {
#pragma unroll
        for (int mi = 0; mi < 4; mi++)
#pragma unroll
            for (int half = 0; half < 2; half++) {
                int r = r0 + mi * 16 + half * 8;
                if (r < NN) {
                    atomicAdd(&g_as1[r * 8 + head], ssum[mi * 2 + half]);
                    atomicAdd(&g_ad1[r * 8 + head], dsum[mi * 2 + half]);
                }
            }
    }
}

// ===== layer1 SINGLE-PASS aggregate: acc += exp*h, den += exp; scale at end =====
__global__ void __launch_bounds__(128) k_agg1(const float* __restrict__ b1) {
    __shared__ float part[4][256];
    __shared__ float sden[4][8];
    __shared__ float sinv[8];
    int d = blockIdx.x;
    int t = threadIdx.x;
    int lane = t & 31;
    int wrp  = t >> 5;
    int start = g_off[d];
    int deg   = g_deg[d];
    int h = lane >> 2;
    float adh = g_ad1[d * 8 + h];

    float acc[8];
#pragma unroll
    for (int k = 0; k < 8; k++) acc[k] = 0.0f;
    float den = 0.0f;

    for (int j = wrp; j < deg; j += 4) {
        int2 e = g_edge[start + j];
        float ew = __int_as_float(e.y);
        float v = g_as1[e.x * 8 + h] + adh;
        v = (v > 0.0f) ? v : NEGSL * v;
        float ex = __expf(v * ew);
        den += ex;
        const float4* p = reinterpret_cast<const float4*>(g_h1 + e.x * 256 + lane * 8);
        float4 a = p[0];
        float4 b = p[1];
        acc[0] += ex * a.x; acc[1] += ex * a.y;
        acc[2] += ex * a.z; acc[3] += ex * a.w;
        acc[4] += ex * b.x; acc[5] += ex * b.y;
        acc[6] += ex * b.z; acc[7] += ex * b.w;
    }

    int fb = lane * 8;
    *reinterpret_cast<float4*>(&part[wrp][fb])     = make_float4(acc[0], acc[1], acc[2], acc[3]);
    *reinterpret_cast<float4*>(&part[wrp][fb + 4]) = make_float4(acc[4], acc[5], acc[6], acc[7]);
    if ((lane & 3) == 0) sden[wrp][h] = den;   // 4 lanes per head computed identical den
    __syncthreads();
    if (t < 8) sinv[t] = 1.0f / (sden[0][t] + sden[1][t] + sden[2][t] + sden[3][t] + EPSF);
    __syncthreads();

    for (int f = t; f < 256; f += 128) {
        float v = (part[0][f] + part[1][f] + part[2][f] + part[3][f]) * sinv[f >> 5] + b1[f];
        g_hx[d * 256 + f] = (v > 0.0f) ? v : (__expf(v) - 1.0f);
    }
}

// ===== GEMM2 (3xTF32 mma) + fused att2: g_z2 = g_hx @ W2 =====
__global__ void __launch_bounds__(128) k_gemm2(const float* __restrict__ att_s,
                                               const float* __restrict__ att_d) {
    int wg = blockIdx.x * 4 + (threadIdx.x >> 5);
    if (wg >= NN / 16) return;
    int lane = threadIdx.x & 31;
    int m0 = wg * 16;
    int r  = lane >> 2;
    int cq = lane & 3;

    float c[2][4];
#pragma unroll
    for (int nt = 0; nt < 2; nt++)
#pragma unroll
        for (int i = 0; i < 4; i++) c[nt][i] = 0.0f;

    const float* A0 = g_hx + (m0 + r) * 256 + cq;
    const float* A1 = g_hx + (m0 + r + 8) * 256 + cq;

#pragma unroll 4
    for (int kg = 0; kg < 32; kg++) {
        float f0 = A0[kg * 8],     f1 = A1[kg * 8];
        float f2 = A0[kg * 8 + 4], f3 = A1[kg * 8 + 4];
        unsigned h0 = f2tf(f0), h1 = f2tf(f1), h2 = f2tf(f2), h3 = f2tf(f3);
        unsigned l0 = f2tf(f0 - __uint_as_float(h0));
        unsigned l1 = f2tf(f1 - __uint_as_float(h1));
        unsigned l2 = f2tf(f2 - __uint_as_float(h2));
        unsigned l3 = f2tf(f3 - __uint_as_float(h3));
#pragma unroll
        for (int nt = 0; nt < 2; nt++) {
            int fidx = (((kg * 2 + nt) * 32 + lane) << 1);
            uint2 bh = *reinterpret_cast<const uint2*>(g_B2hi + fidx);
            uint2 bl = *reinterpret_cast<const uint2*>(g_B2lo + fidx);
            asm volatile(
                "mma.sync.aligned.m16n8k8.row.col.f32.tf32.tf32.f32 "
                "{%0,%1,%2,%3}, {%4,%5,%6,%7}, {%8,%9}, {%0,%1,%2,%3};"
                : "+f"(c[nt][0]), "+f"(c[nt][1]), "+f"(c[nt][2]), "+f"(c[nt][3])
                : "r"(h0), "r"(h1), "r"(h2), "r"(h3), "r"(bh.x), "r"(bh.y));
            asm volatile(
                "mma.sync.aligned.m16n8k8.row.col.f32.tf32.tf32.f32 "
                "{%0,%1,%2,%3}, {%4,%5,%6,%7}, {%8,%9}, {%0,%1,%2,%3};"
                : "+f"(c[nt][0]), "+f"(c[nt][1]), "+f"(c[nt][2]), "+f"(c[nt][3])
                : "r"(l0), "r"(l1), "r"(l2), "r"(l3), "r"(bh.x), "r"(bh.y));
            asm volatile(
                "mma.sync.aligned.m16n8k8.row.col.f32.tf32.tf32.f32 "
                "{%0,%1,%2,%3}, {%4,%5,%6,%7}, {%8,%9}, {%0,%1,%2,%3};"
                : "+f"(c[nt][0]), "+f"(c[nt][1]), "+f"(c[nt][2]), "+f"(c[nt][3])
                : "r"(h0), "r"(h1), "r"(h2), "r"(h3), "r"(bl.x), "r"(bl.y));
        }
    }

#pragma unroll
    for (int nt = 0; nt < 2; nt++) {
        *reinterpret_cast<float2*>(g_z2 + (m0 + r) * 16 + nt * 8 + cq * 2) =
            make_float2(c[nt][0], c[nt][1]);
        *reinterpret_cast<float2*>(g_z2 + (m0 + r + 8) * 16 + nt * 8 + cq * 2) =
            make_float2(c[nt][2], c[nt][3]);
    }

    float sA = 0.f, dA = 0.f, sB = 0.f, dB = 0.f;
#pragma unroll
    for (int nt = 0; nt < 2; nt++)
#pragma unroll
        for (int b = 0; b < 2; b++) {
            int col = nt * 8 + cq * 2 + b;
            float as_ = att_s[col], ad_ = att_d[col];
            sA += c[nt][b]     * as_;  dA += c[nt][b]     * ad_;
            sB += c[nt][2 + b] * as_;  dB += c[nt][2 + b] * ad_;
        }
    sA += __shfl_xor_sync(0xffffffffu, sA, 1); sA += __shfl_xor_sync(0xffffffffu, sA, 2);
    dA += __shfl_xor_sync(0xffffffffu, dA, 1); dA += __shfl_xor_sync(0xffffffffu, dA, 2);
    sB += __shfl_xor_sync(0xffffffffu, sB, 1); sB += __shfl_xor_sync(0xffffffffu, sB, 2);
    dB += __shfl_xor_sync(0xffffffffu, dB, 1); dB += __shfl_xor_sync(0xffffffffu, dB, 2);
    if (cq == 0) {
        g_as2[m0 + r]     = sA;  g_ad2[m0 + r]     = dA;
        g_as2[m0 + r + 8] = sB;  g_ad2[m0 + r + 8] = dB;
    }
}

// ===== layer2 SINGLE-PASS aggregate: warp per node =====
__global__ void k_agg2(const float* __restrict__ b2, float* __restrict__ out) {
    int d = blockIdx.x * (blockDim.x >> 5) + (threadIdx.x >> 5);
    if (d >= NN) return;
    int lane  = threadIdx.x & 31;
    int start = g_off[d];
    int deg   = g_deg[d];
    float ad = g_ad2[d];

    int c = lane & 15, jq = lane >> 4;
    float acc = 0.0f, den = 0.0f;
    for (int j = jq; j < deg; j += 2) {
        int2 e = g_edge[start + j];
        float w = __int_as_float(e.y);
        float v = g_as2[e.x] + ad;
        v = (v > 0.0f) ? v : NEGSL * v;
        float ex = __expf(v * w);
        den += ex;
        acc += ex * g_z2[e.x * 16 + c];
    }
    acc += __shfl_xor_sync(0xffffffffu, acc, 16);
    den += __shfl_xor_sync(0xffffffffu, den, 16);
    if (lane < 16) out[d * 16 + c] = acc / (den + EPSF) + b2[c];
}

// ================= launch ==================================================
extern "C" void kernel_launch(void* const* d_in, const int* in_sizes, int n_in,
                              void* d_out, int out_size) {
    const float* x    = (const float*)d_in[0];
    const int*   ei   = (const int*)  d_in[1];
    const float* ew   = (const float*)d_in[2];
    const float* W1   = (const float*)d_in[3];
    const float* as1  = (const float*)d_in[4];
    const float* ad1  = (const float*)d_in[5];
    const float* b1   = (const float*)d_in[6];
    const float* W2   = (const float*)d_in[7];
    const float* as2  = (const float*)d_in[8];
    const float* ad2  = (const float*)d_in[9];
    const float* b2   = (const float*)d_in[10];
    float* out = (float*)d_out;
    const int* src = ei;
    const int* dst = ei + NE;

    const int TB = 256;

    // fork a side stream for the CSR build (capture-safe fork-join pattern).
    // Created fresh each call and never destroyed (host-side objects only;
    // destroying mid-capture would invalidate the graph).
    cudaStream_t s2;
    cudaEvent_t evFork, evJoin;
    cudaStreamCreateWithFlags(&s2, cudaStreamNonBlocking);
    cudaEventCreateWithFlags(&evFork, cudaEventDisableTiming);
    cudaEventCreateWithFlags(&evJoin, cudaEventDisableTiming);

    cudaEventRecord(evFork, 0);
    cudaStreamWaitEvent(s2, evFork, 0);

    // ---- stream 2: CSR build ----
    k_initdeg<<<(NN + TB - 1) / TB, TB, 0, s2>>>();
    k_hist   <<<(ET + TB - 1) / TB, TB, 0, s2>>>(dst);
    k_scan   <<<1, 1024, 0, s2>>>();
    k_scatter<<<(ET + TB - 1) / TB, TB, 0, s2>>>(src, dst, ew);
    cudaEventRecord(evJoin, s2);

    // ---- default stream: prep + GEMM1 (independent of CSR) ----
    k_pre<<<(PREP_W1 + PREP_W2 + PREP_AS + TB - 1) / TB, TB>>>(W1, W2);
    dim3 g1(2, (NN + 127) / 128);
    k_gemm1<<<g1, 256>>>(x, as1, ad1);

    // join: aggregate needs both CSR and h1/att1
    cudaStreamWaitEvent(0, evJoin, 0);

    k_agg1 <<<NN, 128>>>(b1);
    k_gemm2<<<(NN / 16 + 3) / 4, 128>>>(as2, ad2);
    k_agg2 <<<(NN + 7) / 8, TB>>>(b2, out);
}

// round 14
// speedup vs baseline: 3.3866x; 1.1372x over previous
#include <cuda_runtime.h>
#include <cuda_bf16.h>
#include <cuda_fp16.h>

// ---------------- problem constants ----------------
#define NN    20000            // nodes
#define NE    320000           // edges (without self loops)
#define ET    (NE + NN)        // 340000
#define HEADS 8
#define F1    256              // HEADS*HID
#define NC    16
#define NEGSL 0.2f
#define EPSF  1e-16f

// ---------------- device scratch ----------------
__device__ __half   g_h1h [NN * F1];      // x @ W1  (fp16 messages; only agg1 reads)
__device__ float    g_hx  [NN * F1];      // elu(agg1 + b1)
__device__ float    g_as1 [NN * HEADS];   // accumulated in gemm1 epilogue (fp32)
__device__ float    g_ad1 [NN * HEADS];
__device__ float    g_z2  [NN * NC];      // hx @ W2
__device__ float    g_as2 [NN];
__device__ float    g_ad2 [NN];
__device__ int      g_deg [NN];
__device__ int      g_off [NN];
__device__ int      g_cur [NN];
__device__ int2     g_edge[ET];           // {src, w_bits} CSR order (dst implicit)
__device__ unsigned g_Bfrag [2 * 32 * 16 * 32 * 2];   // W1 tf32 fragments
__device__ unsigned g_B2hi  [32 * 2 * 32 * 2];        // W2 tf32 hi fragments
__device__ unsigned g_B2lo  [32 * 2 * 32 * 2];        // W2 tf32 lo fragments

__device__ __forceinline__ unsigned f2tf(float f) {
    unsigned r; asm("cvt.rna.tf32.f32 %0, %1;" : "=r"(r) : "f"(f)); return r;
}

// ====== stream-1 prep: W1/W2 fragment conversion + as1/ad1 zero ======
#define PREP_W1 65536
#define PREP_W2 4096
#define PREP_AS (NN * HEADS)
__global__ void k_pre(const float* __restrict__ W1, const float* __restrict__ W2) {
    int idx = blockIdx.x * blockDim.x + threadIdx.x;
    if (idx < PREP_W1) {
        int k = idx >> 8, n = idx & 255;
        int nb = n >> 7, ln = n & 127;
        int nt = ln >> 3;
        int lane = ((ln & 7) << 2) + (k & 3);
        int reg = ((k & 7) >= 4) ? 1 : 0;
        int kg = k >> 3;
        g_Bfrag[((((nb * 32 + kg) * 16 + nt) * 32 + lane) << 1) + reg] = f2tf(W1[k * 256 + n]);
    } else if (idx < PREP_W1 + PREP_W2) {
        int i = idx - PREP_W1;
        int k = i >> 4, n = i & 15;
        int nt = n >> 3;
        int lane = ((n & 7) << 2) + (k & 3);
        int reg = ((k & 7) >= 4) ? 1 : 0;
        int kg = k >> 3;
        int base = (((kg * 2 + nt) * 32 + lane) << 1) + reg;
        float w  = W2[k * 16 + n];
        unsigned hi = f2tf(w);
        g_B2hi[base] = hi;
        g_B2lo[base] = f2tf(w - __uint_as_float(hi));
    } else if (idx < PREP_W1 + PREP_W2 + PREP_AS) {
        int i = idx - PREP_W1 - PREP_W2;
        g_as1[i] = 0.0f;
        g_ad1[i] = 0.0f;
    }
}

// ====== stream-2: CSR build ======
__global__ void k_initdeg() {
    int i = blockIdx.x * blockDim.x + threadIdx.x;
    if (i < NN) g_deg[i] = 0;
}

__global__ void k_hist(const int* __restrict__ dst) {
    int e = blockIdx.x * blockDim.x + threadIdx.x;
    if (e >= ET) return;
    int d = (e < NE) ? dst[e] : (e - NE);
    atomicAdd(&g_deg[d], 1);
}

__global__ void k_scan() {
    __shared__ int part[1024];
    const int C = 20;                       // 1024*20 = 20480 >= NN
    int t = threadIdx.x;
    int base = t * C;
    int sum = 0;
    for (int i = 0; i < C; i++) { int idx = base + i; if (idx < NN) sum += g_deg[idx]; }
    part[t] = sum;
    __syncthreads();
    for (int o = 1; o < 1024; o <<= 1) {
        int v = (t >= o) ? part[t - o] : 0;
        __syncthreads();
        part[t] += v;
        __syncthreads();
    }
    int run = (t == 0) ? 0 : part[t - 1];
    for (int i = 0; i < C; i++) {
        int idx = base + i;
        if (idx < NN) { g_off[idx] = run; g_cur[idx] = run; run += g_deg[idx]; }
    }
}

__global__ void k_scatter(const int* __restrict__ src, const int* __restrict__ dst,
                          const float* __restrict__ ew) {
    int e = blockIdx.x * blockDim.x + threadIdx.x;
    if (e >= ET) return;
    int s, d; float w;
    if (e < NE) { s = src[e]; d = dst[e]; w = ew[e]; }
    else        { s = d = e - NE; w = 1.0f; }
    int pos = atomicAdd(&g_cur[d], 1);
    g_edge[pos] = make_int2(s, __float_as_int(w));
}

// ===== GEMM1 (tf32 mma) + fused att1 epilogue: g_h1h = fp16(x @ W1) =====
// block tile 128x128, 8 warps as 2(m) x 4(n), warp tile 64x32 (= one head)
__global__ void __launch_bounds__(256) k_gemm1(const float* __restrict__ A,
                                               const float* __restrict__ att_s,
                                               const float* __restrict__ att_d) {
    __shared__ unsigned sA[8 * 2 * 4 * 32];
    const int t    = threadIdx.x;
    const int lane = t & 31;
    const int wid  = t >> 5;
    const int wm   = wid & 1;
    const int wn   = wid >> 1;
    const int m0   = blockIdx.y * 128;
    const int nb   = blockIdx.x;            // n-half (0/1)

    float c[4][4][4];
#pragma unroll
    for (int a = 0; a < 4; a++)
#pragma unroll
        for (int b = 0; b < 4; b++)
#pragma unroll
            for (int r = 0; r < 4; r++) c[a][b][r] = 0.0f;

    const int mA  = t >> 1;
    const int kqA = (t & 1) * 2;

    for (int k0 = 0; k0 < 256; k0 += 16) {
#pragma unroll
        for (int q = 0; q < 2; q++) {
            int kq = kqA + q;
            float4 av = make_float4(0.f, 0.f, 0.f, 0.f);
            int gr = m0 + mA;
            if (gr < NN) av = *reinterpret_cast<const float4*>(A + gr * 256 + k0 + kq * 4);
            int rr  = mA & 15, mt = mA >> 4;
            int ks  = kq >> 1;
            int reg = (rr >> 3) + (kq & 1) * 2;
            int lb  = (rr & 7) * 4;
            unsigned* p = sA + (((mt * 2 + ks) * 4 + reg) * 32 + lb);
            p[0] = f2tf(av.x); p[1] = f2tf(av.y); p[2] = f2tf(av.z); p[3] = f2tf(av.w);
        }
        __syncthreads();

        int kg0 = k0 >> 3;
#pragma unroll
        for (int ks = 0; ks < 2; ks++) {
            unsigned a[4][4], b[4][2];
#pragma unroll
            for (int mi = 0; mi < 4; mi++) {
                int mt = wm * 4 + mi;
#pragma unroll
                for (int r = 0; r < 4; r++)
                    a[mi][r] = sA[((mt * 2 + ks) * 4 + r) * 32 + lane];
            }
#pragma unroll
            for (int ni = 0; ni < 4; ni++) {
                int nt = wn * 4 + ni;
                const unsigned* bp = g_Bfrag +
                    ((((nb * 32 + kg0 + ks) * 16 + nt) * 32 + lane) << 1);
                uint2 bv = *reinterpret_cast<const uint2*>(bp);
                b[ni][0] = bv.x; b[ni][1] = bv.y;
            }
#pragma unroll
            for (int mi = 0; mi < 4; mi++)
#pragma unroll
                for (int ni = 0; ni < 4; ni++) {
                    asm volatile(
                        "mma.sync.aligned.m16n8k8.row.col.f32.tf32.tf32.f32 "
                        "{%0,%1,%2,%3}, {%4,%5,%6,%7}, {%8,%9}, {%0,%1,%2,%3};"
                        : "+f"(c[mi][ni][0]), "+f"(c[mi][ni][1]),
                          "+f"(c[mi][ni][2]), "+f"(c[mi][ni][3])
                        : "r"(a[mi][0]), "r"(a[mi][1]), "r"(a[mi][2]), "r"(a[mi][3]),
                          "r"(b[ni][0]), "r"(b[ni][1]));
                }
        }
        __syncthreads();
    }

    // ---- epilogue: write fp16 messages + fused att1 partials (fp32) ----
    int r0 = m0 + wm * 64 + (lane >> 2);
    int c0 = nb * 128 + wn * 32 + (lane & 3) * 2;
#pragma unroll
    for (int mi = 0; mi < 4; mi++) {
        int r = r0 + mi * 16;
#pragma unroll
        for (int ni = 0; ni < 4; ni++) {
            int cc = c0 + ni * 8;
            if (r < NN)
                *reinterpret_cast<__half2*>(g_h1h + r * 256 + cc) =
                    __floats2half2_rn(c[mi][ni][0], c[mi][ni][1]);
            if (r + 8 < NN)
                *reinterpret_cast<__half2*>(g_h1h + (r + 8) * 256 + cc) =
                    __floats2half2_rn(c[mi][ni][2], c[mi][ni][3]);
        }
    }

    int head = nb * 4 + wn;
    float asv[8], adv[8];
#pragma unroll
    for (int ni = 0; ni < 4; ni++)
#pragma unroll
        for (int b = 0; b < 2; b++) {
            asv[ni * 2 + b] = att_s[c0 + ni * 8 + b];
            adv[ni * 2 + b] = att_d[c0 + ni * 8 + b];
        }
    float ssum[8], dsum[8];
#pragma unroll
    for (int mi = 0; mi < 4; mi++)
#pragma unroll
        for (int half = 0; half < 2; half++) {
            float s = 0.f, dd = 0.f;
#pragma unroll
            for (int ni = 0; ni < 4; ni++)
#pragma unroll
                for (int b = 0; b < 2; b++) {
                    float v = c[mi][ni][half * 2 + b];
                    s  += v * asv[ni * 2 + b];
                    dd += v * adv[ni * 2 + b];
                }
            ssum[mi * 2 + half] = s;
            dsum[mi * 2 + half] = dd;
        }
#pragma unroll
    for (int i = 0; i < 8; i++) {
        ssum[i] += __shfl_xor_sync(0xffffffffu, ssum[i], 1);
        ssum[i] += __shfl_xor_sync(0xffffffffu, ssum[i], 2);
        dsum[i] += __shfl_xor_sync(0xffffffffu, dsum[i], 1);
        dsum[i] += __shfl_xor_sync(0xffffffffu, dsum[i], 2);
    }
    if ((lane & 3) == 0) {
#pragma unroll
        for (int mi = 0; mi < 4; mi++)
#pragma unroll
            for (int half = 0; half < 2; half++) {
                int r = r0 + mi * 16 + half * 8;
                if (r < NN) {
                    atomicAdd(&g_as1[r * 8 + head], ssum[mi * 2 + half]);
                    atomicAdd(&g_ad1[r * 8 + head], dsum[mi * 2 + half]);
                }
            }
    }
}

// ===== layer1 SINGLE-PASS aggregate (fp16 gather): block(128) per node =====
__global__ void __launch_bounds__(128) k_agg1(const float* __restrict__ b1) {
    __shared__ float part[4][256];
    __shared__ float sden[4][8];
    __shared__ float sinv[8];
    int d = blockIdx.x;
    int t = threadIdx.x;
    int lane = t & 31;
    int wrp  = t >> 5;
    int start = g_off[d];
    int deg   = g_deg[d];
    int h = lane >> 2;
    float adh = g_ad1[d * 8 + h];

    float acc[8];
#pragma unroll
    for (int k = 0; k < 8; k++) acc[k] = 0.0f;
    float den = 0.0f;

    for (int j = wrp; j < deg; j += 4) {
        int2 e = g_edge[start + j];
        float ew = __int_as_float(e.y);
        float v = g_as1[e.x * 8 + h] + adh;
        v = (v > 0.0f) ? v : NEGSL * v;
        float ex = __expf(v * ew);
        den += ex;
        // 8 halves = 16 bytes per lane, one uint4
        uint4 raw = *reinterpret_cast<const uint4*>(g_h1h + e.x * 256 + lane * 8);
        float2 f0 = __half22float2(*reinterpret_cast<__half2*>(&raw.x));
        float2 f1 = __half22float2(*reinterpret_cast<__half2*>(&raw.y));
        float2 f2 = __half22float2(*reinterpret_cast<__half2*>(&raw.z));
        float2 f3 = __half22float2(*reinterpret_cast<__half2*>(&raw.w));
        acc[0] += ex * f0.x; acc[1] += ex * f0.y;
        acc[2] += ex * f1.x; acc[3] += ex * f1.y;
        acc[4] += ex * f2.x; acc[5] += ex * f2.y;
        acc[6] += ex * f3.x; acc[7] += ex * f3.y;
    }

    int fb = lane * 8;
    *reinterpret_cast<float4*>(&part[wrp][fb])     = make_float4(acc[0], acc[1], acc[2], acc[3]);
    *reinterpret_cast<float4*>(&part[wrp][fb + 4]) = make_float4(acc[4], acc[5], acc[6], acc[7]);
    if ((lane & 3) == 0) sden[wrp][h] = den;   // 4 lanes per head computed identical den
    __syncthreads();
    if (t < 8) sinv[t] = 1.0f / (sden[0][t] + sden[1][t] + sden[2][t] + sden[3][t] + EPSF);
    __syncthreads();

    for (int f = t; f < 256; f += 128) {
        float v = (part[0][f] + part[1][f] + part[2][f] + part[3][f]) * sinv[f >> 5] + b1[f];
        g_hx[d * 256 + f] = (v > 0.0f) ? v : (__expf(v) - 1.0f);
    }
}

// ===== GEMM2 (3xTF32 mma) + fused att2: g_z2 = g_hx @ W2 =====
__global__ void __launch_bounds__(128) k_gemm2(const float* __restrict__ att_s,
                                               const float* __restrict__ att_d) {
    int wg = blockIdx.x * 4 + (threadIdx.x >> 5);
    if (wg >= NN / 16) return;
    int lane = threadIdx.x & 31;
    int m0 = wg * 16;
    int r  = lane >> 2;
    int cq = lane & 3;

    float c[2][4];
#pragma unroll
    for (int nt = 0; nt < 2; nt++)
#pragma unroll
        for (int i = 0; i < 4; i++) c[nt][i] = 0.0f;

    const float* A0 = g_hx + (m0 + r) * 256 + cq;
    const float* A1 = g_hx + (m0 + r + 8) * 256 + cq;

#pragma unroll 4
    for (int kg = 0; kg < 32; kg++) {
        float f0 = A0[kg * 8],     f1 = A1[kg * 8];
        float f2 = A0[kg * 8 + 4], f3 = A1[kg * 8 + 4];
        unsigned h0 = f2tf(f0), h1 = f2tf(f1), h2 = f2tf(f2), h3 = f2tf(f3);
        unsigned l0 = f2tf(f0 - __uint_as_float(h0));
        unsigned l1 = f2tf(f1 - __uint_as_float(h1));
        unsigned l2 = f2tf(f2 - __uint_as_float(h2));
        unsigned l3 = f2tf(f3 - __uint_as_float(h3));
#pragma unroll
        for (int nt = 0; nt < 2; nt++) {
            int fidx = (((kg * 2 + nt) * 32 + lane) << 1);
            uint2 bh = *reinterpret_cast<const uint2*>(g_B2hi + fidx);
            uint2 bl = *reinterpret_cast<const uint2*>(g_B2lo + fidx);
            asm volatile(
                "mma.sync.aligned.m16n8k8.row.col.f32.tf32.tf32.f32 "
                "{%0,%1,%2,%3}, {%4,%5,%6,%7}, {%8,%9}, {%0,%1,%2,%3};"
                : "+f"(c[nt][0]), "+f"(c[nt][1]), "+f"(c[nt][2]), "+f"(c[nt][3])
                : "r"(h0), "r"(h1), "r"(h2), "r"(h3), "r"(bh.x), "r"(bh.y));
            asm volatile(
                "mma.sync.aligned.m16n8k8.row.col.f32.tf32.tf32.f32 "
                "{%0,%1,%2,%3}, {%4,%5,%6,%7}, {%8,%9}, {%0,%1,%2,%3};"
                : "+f"(c[nt][0]), "+f"(c[nt][1]), "+f"(c[nt][2]), "+f"(c[nt][3])
                : "r"(l0), "r"(l1), "r"(l2), "r"(l3), "r"(bh.x), "r"(bh.y));
            asm volatile(
                "mma.sync.aligned.m16n8k8.row.col.f32.tf32.tf32.f32 "
                "{%0,%1,%2,%3}, {%4,%5,%6,%7}, {%8,%9}, {%0,%1,%2,%3};"
                : "+f"(c[nt][0]), "+f"(c[nt][1]), "+f"(c[nt][2]), "+f"(c[nt][3])
                : "r"(h0), "r"(h1), "r"(h2), "r"(h3), "r"(bl.x), "r"(bl.y));
        }
    }

#pragma unroll
    for (int nt = 0; nt < 2; nt++) {
        *reinterpret_cast<float2*>(g_z2 + (m0 + r) * 16 + nt * 8 + cq * 2) =
            make_float2(c[nt][0], c[nt][1]);
        *reinterpret_cast<float2*>(g_z2 + (m0 + r + 8) * 16 + nt * 8 + cq * 2) =
            make_float2(c[nt][2], c[nt][3]);
    }

    float sA = 0.f, dA = 0.f, sB = 0.f, dB = 0.f;
#pragma unroll
    for (int nt = 0; nt < 2; nt++)
#pragma unroll
        for (int b = 0; b < 2; b++) {
            int col = nt * 8 + cq * 2 + b;
            float as_ = att_s[col], ad_ = att_d[col];
            sA += c[nt][b]     * as_;  dA += c[nt][b]     * ad_;
            sB += c[nt][2 + b] * as_;  dB += c[nt][2 + b] * ad_;
        }
    sA += __shfl_xor_sync(0xffffffffu, sA, 1); sA += __shfl_xor_sync(0xffffffffu, sA, 2);
    dA += __shfl_xor_sync(0xffffffffu, dA, 1); dA += __shfl_xor_sync(0xffffffffu, dA, 2);
    sB += __shfl_xor_sync(0xffffffffu, sB, 1); sB += __shfl_xor_sync(0xffffffffu, sB, 2);
    dB += __shfl_xor_sync(0xffffffffu, dB, 1); dB += __shfl_xor_sync(0xffffffffu, dB, 2);
    if (cq == 0) {
        g_as2[m0 + r]     = sA;  g_ad2[m0 + r]     = dA;
        g_as2[m0 + r + 8] = sB;  g_ad2[m0 + r + 8] = dB;
    }
}

// ===== layer2 SINGLE-PASS aggregate: warp per node =====
__global__ void k_agg2(const float* __restrict__ b2, float* __restrict__ out) {
    int d = blockIdx.x * (blockDim.x >> 5) + (threadIdx.x >> 5);
    if (d >= NN) return;
    int lane  = threadIdx.x & 31;
    int start = g_off[d];
    int deg   = g_deg[d];
    float ad = g_ad2[d];

    int c = lane & 15, jq = lane >> 4;
    float acc = 0.0f, den = 0.0f;
    for (int j = jq; j < deg; j += 2) {
        int2 e = g_edge[start + j];
        float w = __int_as_float(e.y);
        float v = g_as2[e.x] + ad;
        v = (v > 0.0f) ? v : NEGSL * v;
        float ex = __expf(v * w);
        den += ex;
        acc += ex * g_z2[e.x * 16 + c];
    }
    acc += __shfl_xor_sync(0xffffffffu, acc, 16);
    den += __shfl_xor_sync(0xffffffffu, den, 16);
    if (lane < 16) out[d * 16 + c] = acc / (den + EPSF) + b2[c];
}

// ================= launch ==================================================
extern "C" void kernel_launch(void* const* d_in, const int* in_sizes, int n_in,
                              void* d_out, int out_size) {
    const float* x    = (const float*)d_in[0];
    const int*   ei   = (const int*)  d_in[1];
    const float* ew   = (const float*)d_in[2];
    const float* W1   = (const float*)d_in[3];
    const float* as1  = (const float*)d_in[4];
    const float* ad1  = (const float*)d_in[5];
    const float* b1   = (const float*)d_in[6];
    const float* W2   = (const float*)d_in[7];
    const float* as2  = (const float*)d_in[8];
    const float* ad2  = (const float*)d_in[9];
    const float* b2   = (const float*)d_in[10];
    float* out = (float*)d_out;
    const int* src = ei;
    const int* dst = ei + NE;

    const int TB = 256;

    // fork a side stream for the CSR build (capture-safe fork-join pattern).
    cudaStream_t s2;
    cudaEvent_t evFork, evJoin;
    cudaStreamCreateWithFlags(&s2, cudaStreamNonBlocking);
    cudaEventCreateWithFlags(&evFork, cudaEventDisableTiming);
    cudaEventCreateWithFlags(&evJoin, cudaEventDisableTiming);

    cudaEventRecord(evFork, 0);
    cudaStreamWaitEvent(s2, evFork, 0);

    // ---- stream 2: CSR build ----
    k_initdeg<<<(NN + TB - 1) / TB, TB, 0, s2>>>();
    k_hist   <<<(ET + TB - 1) / TB, TB, 0, s2>>>(dst);
    k_scan   <<<1, 1024, 0, s2>>>();
    k_scatter<<<(ET + TB - 1) / TB, TB, 0, s2>>>(src, dst, ew);
    cudaEventRecord(evJoin, s2);

    // ---- default stream: prep + GEMM1 (independent of CSR) ----
    k_pre<<<(PREP_W1 + PREP_W2 + PREP_AS + TB - 1) / TB, TB>>>(W1, W2);
    dim3 g1(2, (NN + 127) / 128);
    k_gemm1<<<g1, 256>>>(x, as1, ad1);

    // join: aggregate needs both CSR and h1/att1
    cudaStreamWaitEvent(0, evJoin, 0);

    k_agg1 <<<NN, 128>>>(b1);
    k_gemm2<<<(NN / 16 + 3) / 4, 128>>>(as2, ad2);
    k_agg2 <<<(NN + 7) / 8, TB>>>(b2, out);
}